// round 12
// baseline (speedup 1.0000x reference)
#include <cuda_runtime.h>
#include <math.h>

#define NN 10000
#define EE 160000
#define PP 4000
#define HT_SIZE 16384
#define HT_MASK 16383
#define NOTF 0x7fffffff

typedef unsigned long long ull;

// ---------------- f32x2 packed helpers (Blackwell) ----------------
__device__ __forceinline__ ull pack2(float lo, float hi) {
    ull r; asm("mov.b64 %0,{%1,%2};" : "=l"(r) : "f"(lo), "f"(hi)); return r;
}
__device__ __forceinline__ float2 unpack2(ull v) {
    float2 r; asm("mov.b64 {%0,%1},%2;" : "=f"(r.x), "=f"(r.y) : "l"(v)); return r;
}
__device__ __forceinline__ ull fma2(ull a, ull b, ull c) {
    ull d; asm("fma.rn.f32x2 %0,%1,%2,%3;" : "=l"(d) : "l"(a), "l"(b), "l"(c)); return d;
}
__device__ __forceinline__ ull mul2(ull a, ull b) {
    ull d; asm("mul.rn.f32x2 %0,%1,%2;" : "=l"(d) : "l"(a), "l"(b)); return d;
}
__device__ __forceinline__ ull add2(ull a, ull b) {
    ull d; asm("add.rn.f32x2 %0,%1,%2;" : "=l"(d) : "l"(a), "l"(b)); return d;
}

// ---------------- scratch (device globals; no allocation) ----------------
__device__ float g_xl[NN * 256];
__device__ float g_xr[NN * 256];
__device__ float g_h[NN * 256];
__device__ int g_cnt[NN];
__device__ int g_rowstart[NN + 1];
__device__ int g_cursor[NN];
__device__ __align__(16) float4 g_eac[EE];   // {ea0, ea1, ea2, src_bits}
__device__ int g_htk[HT_SIZE];
__device__ int g_htv[HT_SIZE];
__device__ int g_done;
__device__ int g_nctr[2];                    // work-steal counters (per gat layer)

__device__ __forceinline__ unsigned ht_hash(int key) {
    return ((unsigned)key * 2654435761u) >> 18;
}
__device__ __forceinline__ int ht_find(int key) {
    unsigned slot = ht_hash(key) & HT_MASK;
    while (true) {
        int kk = g_htk[slot];
        if (kk == key) return g_htv[slot];
        if (kk == -1) return NOTF;
        slot = (slot + 1) & HT_MASK;
    }
}

// ---------------- K1: init hash/counts (blocks 0..63) + layer-1 GEMM ----------------
__global__ __launch_bounds__(256) void k_init_gemm1(
    const float* __restrict__ X,
    const float* __restrict__ Wl, const float* __restrict__ bl,
    const float* __restrict__ Wr, const float* __restrict__ br) {
    if (blockIdx.x < 64) {
        int i = blockIdx.x * 256 + threadIdx.x;
        if (i < HT_SIZE) { g_htk[i] = -1; g_htv[i] = NOTF; }
        if (i < NN) g_cnt[i] = 0;
        if (i == 0) { g_done = 0; g_nctr[0] = 0; g_nctr[1] = 0; }
        return;
    }
    __shared__ __align__(16) float xs[8 * 16];
    int tid = threadIdx.x;
    int nb = (blockIdx.x - 64) * 16;
    if (tid < 128) {
        int i = tid / 8, k = tid % 8;
        xs[k * 16 + i] = X[(nb + i) * 8 + k];
    }
    __syncthreads();
    ull accl[8], accr[8];
    #pragma unroll
    for (int q = 0; q < 8; q++) { accl[q] = 0ULL; accr[q] = 0ULL; }
    #pragma unroll
    for (int k = 0; k < 8; k++) {
        float wl = __ldg(Wl + k * 256 + tid);
        float wr = __ldg(Wr + k * 256 + tid);
        ull wl2 = pack2(wl, wl);
        ull wr2 = pack2(wr, wr);
        const ulonglong2* xv = reinterpret_cast<const ulonglong2*>(xs + k * 16);
        #pragma unroll
        for (int q2 = 0; q2 < 4; q2++) {
            ulonglong2 a = xv[q2];
            accl[q2 * 2 + 0] = fma2(a.x, wl2, accl[q2 * 2 + 0]);
            accl[q2 * 2 + 1] = fma2(a.y, wl2, accl[q2 * 2 + 1]);
            accr[q2 * 2 + 0] = fma2(a.x, wr2, accr[q2 * 2 + 0]);
            accr[q2 * 2 + 1] = fma2(a.y, wr2, accr[q2 * 2 + 1]);
        }
    }
    float bvl = bl[tid], bvr = br[tid];
    #pragma unroll
    for (int q = 0; q < 8; q++) {
        float2 vl = unpack2(accl[q]);
        float2 vr = unpack2(accr[q]);
        g_xl[(nb + 2 * q + 0) * 256 + tid] = vl.x + bvl;
        g_xl[(nb + 2 * q + 1) * 256 + tid] = vl.y + bvl;
        g_xr[(nb + 2 * q + 0) * 256 + tid] = vr.x + bvr;
        g_xr[(nb + 2 * q + 1) * 256 + tid] = vr.y + bvr;
    }
}

// ---------------- K2: count degrees + hash-insert + (last block) prefix scan ----------------
__global__ __launch_bounds__(256) void count_insert_scan_kernel(
    const int* __restrict__ dst, const int* __restrict__ pe) {
    int e = blockIdx.x * blockDim.x + threadIdx.x;
    if (e < EE) atomicAdd(&g_cnt[dst[e]], 1);
    if (e < 2 * PP) {
        int p = e >> 1;
        int i = pe[p * 2 + 0];
        int j = pe[p * 2 + 1];
        int key = (e & 1) ? (j * NN + i) : (i * NN + j);
        unsigned slot = ht_hash(key) & HT_MASK;
        while (true) {
            int old = atomicCAS(&g_htk[slot], -1, key);
            if (old == -1 || old == key) break;
            slot = (slot + 1) & HT_MASK;
        }
    }
    __threadfence();
    __shared__ int isLast;
    if (threadIdx.x == 0) {
        int v = atomicAdd(&g_done, 1);
        isLast = (v == (int)gridDim.x - 1);
    }
    __syncthreads();
    if (!isLast) return;

    __shared__ int part[256];
    int t = threadIdx.x;
    const int CH = 40;
    int base = t * CH;
    int s = 0;
    for (int i = 0; i < CH; i++) {
        int idx = base + i;
        if (idx < NN) s += g_cnt[idx];
    }
    part[t] = s;
    __syncthreads();
    for (int off = 1; off < 256; off <<= 1) {
        int v = (t >= off) ? part[t - off] : 0;
        __syncthreads();
        part[t] += v;
        __syncthreads();
    }
    int run = (t > 0) ? part[t - 1] : 0;
    for (int i = 0; i < CH; i++) {
        int idx = base + i;
        if (idx < NN) {
            g_rowstart[idx] = run;
            g_cursor[idx] = run;
            run += g_cnt[idx];
        }
    }
    if (t == 255) g_rowstart[NN] = part[255];
}

// ---------------- K3: scatter packed edge payload into CSR + hash min-scan ----------------
__global__ void scatter_scan_kernel(const int* __restrict__ src, const int* __restrict__ dst,
                                    const float* __restrict__ ea) {
    int e = blockIdx.x * blockDim.x + threadIdx.x;
    if (e >= EE) return;
    int sN = src[e], dN = dst[e];
    float4 c;
    c.x = __ldg(ea + e * 3 + 0);
    c.y = __ldg(ea + e * 3 + 1);
    c.z = __ldg(ea + e * 3 + 2);
    c.w = __int_as_float(sN);
    int pos = atomicAdd(&g_cursor[dN], 1);
    g_eac[pos] = c;
    int key = sN * NN + dN;
    unsigned slot = ht_hash(key) & HT_MASK;
    while (true) {
        int kk = g_htk[slot];
        if (kk == -1) return;
        if (kk == key) { atomicMin(&g_htv[slot], e); return; }
        slot = (slot + 1) & HT_MASK;
    }
}

// ---------------- GATv2 edge phase: one warp per node (8 ch/lane), work-stealing,
// ---------------- 2-deep software pipeline (eac AND xl prefetched one edge ahead) ----------------
__global__ void __launch_bounds__(128, 4) gat_edge(
    const float* __restrict__ We,
    const float* __restrict__ att, const float* __restrict__ bias, int layer) {
    int l = threadIdx.x & 31;
    int ch0 = l * 8;
    int head = l >> 3;
    int hk = (l & 7) * 8;

    // packed per-lane constants (channel pairs)
    ull wv0[4], wv1[4], wv2[4], av2[4];
    #pragma unroll
    for (int k = 0; k < 4; k++) {
        wv0[k] = pack2(We[0 * 256 + ch0 + 2 * k], We[0 * 256 + ch0 + 2 * k + 1]);
        wv1[k] = pack2(We[1 * 256 + ch0 + 2 * k], We[1 * 256 + ch0 + 2 * k + 1]);
        wv2[k] = pack2(We[2 * 256 + ch0 + 2 * k], We[2 * 256 + ch0 + 2 * k + 1]);
        av2[k] = pack2(att[head * 64 + hk + 2 * k], att[head * 64 + hk + 2 * k + 1]);
    }
    const ull C06 = pack2(0.6f, 0.6f);
    const ull C04 = pack2(0.4f, 0.4f);
    const ull ABSM = 0x7FFFFFFF7FFFFFFFULL;

    while (true) {
        int node;
        if (l == 0) node = atomicAdd(&g_nctr[layer], 1);
        node = __shfl_sync(0xffffffffu, node, 0);
        if (node >= NN) break;

        ull xr2[4];
        {
            float4 ra = *reinterpret_cast<const float4*>(g_xr + node * 256 + ch0);
            float4 rb = *reinterpret_cast<const float4*>(g_xr + node * 256 + ch0 + 4);
            xr2[0] = pack2(ra.x, ra.y); xr2[1] = pack2(ra.z, ra.w);
            xr2[2] = pack2(rb.x, rb.y); xr2[3] = pack2(rb.z, rb.w);
        }
        int s0 = g_rowstart[node];
        int en = g_rowstart[node + 1];
        int last = en - 1;

        float ssum = 0.f;
        ull acc[4] = {0ULL, 0ULL, 0ULL, 0ULL};

        // 2-deep pipeline: edge sp's (eac, xl) loaded an iteration early.
        float4 c_cur, c_nxt, xa_cur, xb_cur;
        if (s0 < en) {
            c_cur = g_eac[s0];
            int sn = __float_as_int(c_cur.w);
            xa_cur = *reinterpret_cast<const float4*>(g_xl + sn * 256 + ch0);
            xb_cur = *reinterpret_cast<const float4*>(g_xl + sn * 256 + ch0 + 4);
            c_nxt = g_eac[min(s0 + 1, last)];
        }
        for (int sp = s0; sp < en; sp++) {
            // issue next edge's gathers before doing this edge's math
            int snn = __float_as_int(c_nxt.w);
            float4 xa_n = *reinterpret_cast<const float4*>(g_xl + snn * 256 + ch0);
            float4 xb_n = *reinterpret_cast<const float4*>(g_xl + snn * 256 + ch0 + 4);
            float4 c_nn = g_eac[min(sp + 2, last)];

            ull ea0 = pack2(c_cur.x, c_cur.x);
            ull ea1 = pack2(c_cur.y, c_cur.y);
            ull ea2 = pack2(c_cur.z, c_cur.z);
            ull x2[4];
            x2[0] = pack2(xa_cur.x, xa_cur.y); x2[1] = pack2(xa_cur.z, xa_cur.w);
            x2[2] = pack2(xb_cur.x, xb_cur.y); x2[3] = pack2(xb_cur.z, xb_cur.w);
            ull dot = 0ULL;
            #pragma unroll
            for (int k = 0; k < 4; k++) {
                ull b = fma2(ea2, wv2[k], fma2(ea1, wv1[k], fma2(ea0, wv0[k], xr2[k])));
                ull t = add2(x2[k], b);
                ull ab = t & ABSM;                       // |t| pairwise
                t = fma2(ab, C04, mul2(t, C06));         // leaky(t,0.2) = 0.6t+0.4|t|
                dot = fma2(t, av2[k], dot);
            }
            float2 d = unpack2(dot);
            float p = d.x + d.y;
            p += __shfl_xor_sync(0xffffffffu, p, 1);
            p += __shfl_xor_sync(0xffffffffu, p, 2);
            p += __shfl_xor_sync(0xffffffffu, p, 4);     // sum over 8 lanes of this head

            float w0 = __expf(p);                        // exact softmax w/o max-shift (logits O(1))
            ssum += w0;
            ull w2 = pack2(w0, w0);
            #pragma unroll
            for (int k = 0; k < 4; k++) acc[k] = fma2(w2, x2[k], acc[k]);

            // rotate pipeline
            c_cur = c_nxt; c_nxt = c_nn;
            xa_cur = xa_n; xb_cur = xb_n;
        }

        float inv = 1.f / (ssum + 1e-16f);
        float4 bva = *reinterpret_cast<const float4*>(bias + ch0);
        float4 bvb = *reinterpret_cast<const float4*>(bias + ch0 + 4);
        float2 a0 = unpack2(acc[0]);
        float2 a1 = unpack2(acc[1]);
        float2 a2 = unpack2(acc[2]);
        float2 a3 = unpack2(acc[3]);
        float vv[8] = {a0.x, a0.y, a1.x, a1.y, a2.x, a2.y, a3.x, a3.y};
        float bb[8] = {bva.x, bva.y, bva.z, bva.w, bvb.x, bvb.y, bvb.z, bvb.w};
        float o[8];
        #pragma unroll
        for (int k = 0; k < 8; k++) {
            float v = fmaf(vv[k], inv, bb[k]);
            o[k] = (v > 0.f) ? v : expm1f(v);
        }
        float* hp = g_h + node * 256 + ch0;
        *reinterpret_cast<float4*>(hp) = make_float4(o[0], o[1], o[2], o[3]);
        *reinterpret_cast<float4*>(hp + 4) = make_float4(o[4], o[5], o[6], o[7]);
    }
}

// ---------------- layer-2 dual GEMM, weight-role split: block computes 32 rows x ONE weight ----------------
#define G2_ROWBLOCKS ((NN + 31) / 32)   // 313
__global__ __launch_bounds__(256) void gemm2(
    const float* __restrict__ Wl, const float* __restrict__ bl,
    const float* __restrict__ Wr, const float* __restrict__ br) {
    __shared__ __align__(16) float xs[256 * 36];
    int tid = threadIdx.x;
    int role = (blockIdx.x >= G2_ROWBLOCKS);                // 0 -> Wl/g_xl, 1 -> Wr/g_xr
    int rb = role ? (blockIdx.x - G2_ROWBLOCKS) : blockIdx.x;
    const float* W = role ? Wr : Wl;
    const float* bv = role ? br : bl;
    float* outp = role ? g_xr : g_xl;
    int nb = rb * 32;
    for (int idx = tid; idx < 32 * 256; idx += 256) {
        int i = idx / 256, k = idx % 256;
        int row = nb + i;
        xs[k * 36 + i] = (row < NN) ? g_h[row * 256 + k] : 0.f;
    }
    __syncthreads();
    ull acc[16];
    #pragma unroll
    for (int q = 0; q < 16; q++) acc[q] = 0ULL;
    #pragma unroll 4
    for (int k = 0; k < 256; k += 2) {
        float w0 = __ldg(W + k * 256 + tid);
        float w1 = __ldg(W + (k + 1) * 256 + tid);
        ull w20 = pack2(w0, w0);
        ull w21 = pack2(w1, w1);
        const ulonglong2* xv0 = reinterpret_cast<const ulonglong2*>(xs + k * 36);
        const ulonglong2* xv1 = reinterpret_cast<const ulonglong2*>(xs + (k + 1) * 36);
        #pragma unroll
        for (int q2 = 0; q2 < 8; q2++) {
            ulonglong2 a0 = xv0[q2];
            acc[q2 * 2 + 0] = fma2(a0.x, w20, acc[q2 * 2 + 0]);
            acc[q2 * 2 + 1] = fma2(a0.y, w20, acc[q2 * 2 + 1]);
        }
        #pragma unroll
        for (int q2 = 0; q2 < 8; q2++) {
            ulonglong2 a1 = xv1[q2];
            acc[q2 * 2 + 0] = fma2(a1.x, w21, acc[q2 * 2 + 0]);
            acc[q2 * 2 + 1] = fma2(a1.y, w21, acc[q2 * 2 + 1]);
        }
    }
    float bb = bv[tid];
    #pragma unroll
    for (int q = 0; q < 16; q++) {
        int r0 = nb + 2 * q, r1 = nb + 2 * q + 1;
        float2 v = unpack2(acc[q]);
        if (r0 < NN) outp[r0 * 256 + tid] = v.x + bb;
        if (r1 < NN) outp[r1 * 256 + tid] = v.y + bb;
    }
}

// ---------------- merged heads: blocks [0,250) edge head (16 edges), [250,875) node head ----------------
#define EDGE_BLOCKS (PP / 16)    // 250
__global__ __launch_bounds__(256) void heads_kernel(
    const int* __restrict__ pe, const float* __restrict__ eattr,
    const float* __restrict__ Wq1, const float* __restrict__ bq1,
    const float* __restrict__ Wq2, const float* __restrict__ bq2,
    const float* __restrict__ Wq3, const float* __restrict__ bq3,
    const float* __restrict__ Wn1, const float* __restrict__ bn1,
    const float* __restrict__ Wn2, const float* __restrict__ bn2,
    const float* __restrict__ Wn3, const float* __restrict__ bn3,
    float* __restrict__ out) {
    __shared__ __align__(16) float pool[11952];
    __shared__ int sidx[16];
    int tid = threadIdx.x;

    if (blockIdx.x < EDGE_BLOCKS) {
        float* efsT = pool;              // [k up to 520][stride 20]
        float* eq1 = pool + 10400;       // [16][64]
        float* eq2 = pool + 11424;       // [16][33]
        int pb = blockIdx.x * 16;
        if (tid < 16) {
            int p = pb + tid;
            int i = pe[p * 2 + 0];
            int j = pe[p * 2 + 1];
            sidx[tid] = min(ht_find(i * NN + j), ht_find(j * NN + i));
        }
        __syncthreads();
        #pragma unroll 1
        for (int e16 = 0; e16 < 16; e16++) {
            int p = pb + e16;
            int i = pe[p * 2 + 0];
            int j = pe[p * 2 + 1];
            int idx = sidx[e16];
            for (int t = tid; t < 515; t += 256) {
                float v;
                if (t < 256) v = g_h[i * 256 + t];
                else if (t < 512) v = g_h[j * 256 + (t - 256)];
                else v = (idx < NOTF) ? eattr[idx * 3 + (t - 512)] : 0.f;
                efsT[t * 20 + e16] = v;
            }
        }
        __syncthreads();
        {
            int oc = tid & 63;
            int grp = tid >> 6;
            ull a01 = 0ULL, a23 = 0ULL;
            const float* base = efsT + grp * 4;
            for (int k = 0; k < 515; k++) {
                float w = __ldg(Wq1 + k * 64 + oc);
                ull w2 = pack2(w, w);
                float4 ef = *reinterpret_cast<const float4*>(base + k * 20);
                a01 = fma2(pack2(ef.x, ef.y), w2, a01);
                a23 = fma2(pack2(ef.z, ef.w), w2, a23);
            }
            float bb = bq1[oc];
            float2 v01 = unpack2(a01);
            float2 v23 = unpack2(a23);
            float v[4] = {v01.x + bb, v01.y + bb, v23.x + bb, v23.y + bb};
            #pragma unroll
            for (int q = 0; q < 4; q++) {
                float a = v[q];
                a = (a > 0.f) ? a : expm1f(a);
                eq1[(grp * 4 + q) * 64 + oc] = a;
            }
        }
        __syncthreads();
        {
            int oc2 = tid & 31;
            int g2 = tid >> 5;
            ull b01 = 0ULL;
            for (int k = 0; k < 64; k++) {
                float w = Wq2[k * 32 + oc2];
                b01 = fma2(pack2(eq1[(g2 * 2 + 0) * 64 + k], eq1[(g2 * 2 + 1) * 64 + k]),
                           pack2(w, w), b01);
            }
            float bb2 = bq2[oc2];
            float2 b = unpack2(b01);
            float b0 = b.x + bb2, b1 = b.y + bb2;
            b0 = (b0 > 0.f) ? b0 : expm1f(b0);
            b1 = (b1 > 0.f) ? b1 : expm1f(b1);
            eq2[(g2 * 2 + 0) * 33 + oc2] = b0;
            eq2[(g2 * 2 + 1) * 33 + oc2] = b1;
        }
        __syncthreads();
        {
            int w8 = tid >> 5;
            int lane = tid & 31;
            #pragma unroll
            for (int q = 0; q < 2; q++) {
                int e = w8 * 2 + q;
                float v = eq2[e * 33 + lane] * Wq3[lane];
                v += __shfl_xor_sync(0xffffffffu, v, 16);
                v += __shfl_xor_sync(0xffffffffu, v, 8);
                v += __shfl_xor_sync(0xffffffffu, v, 4);
                v += __shfl_xor_sync(0xffffffffu, v, 2);
                v += __shfl_xor_sync(0xffffffffu, v, 1);
                if (lane == 0) out[pb + e] = v + bq3[0];
            }
        }
    } else {
        float* hsT = pool;               // [256][stride 20]
        float* eq1 = pool + 5120;        // [16][64]
        float* eq2 = pool + 6144;        // [16][33]
        int nb = (blockIdx.x - EDGE_BLOCKS) * 16;
        for (int t = tid; t < 16 * 256; t += 256) {
            int i = t >> 8;
            int c = t & 255;
            hsT[c * 20 + i] = g_h[(nb + i) * 256 + c];
        }
        __syncthreads();
        {
            int oc = tid & 63;
            int grp = tid >> 6;
            ull a01 = 0ULL, a23 = 0ULL;
            const float* base = hsT + grp * 4;
            for (int k = 0; k < 256; k++) {
                float w = __ldg(Wn1 + k * 64 + oc);
                ull w2 = pack2(w, w);
                float4 hv = *reinterpret_cast<const float4*>(base + k * 20);
                a01 = fma2(pack2(hv.x, hv.y), w2, a01);
                a23 = fma2(pack2(hv.z, hv.w), w2, a23);
            }
            float bb = bn1[oc];
            float2 v01 = unpack2(a01);
            float2 v23 = unpack2(a23);
            float v[4] = {v01.x + bb, v01.y + bb, v23.x + bb, v23.y + bb};
            #pragma unroll
            for (int q = 0; q < 4; q++) {
                float a = v[q];
                a = (a > 0.f) ? a : expm1f(a);
                eq1[(grp * 4 + q) * 64 + oc] = a;
            }
        }
        __syncthreads();
        {
            int oc2 = tid & 31;
            int g2 = tid >> 5;
            ull b01 = 0ULL;
            for (int k = 0; k < 64; k++) {
                float w = Wn2[k * 32 + oc2];
                b01 = fma2(pack2(eq1[(g2 * 2 + 0) * 64 + k], eq1[(g2 * 2 + 1) * 64 + k]),
                           pack2(w, w), b01);
            }
            float bb2 = bn2[oc2];
            float2 b = unpack2(b01);
            float b0 = b.x + bb2, b1 = b.y + bb2;
            b0 = (b0 > 0.f) ? b0 : expm1f(b0);
            b1 = (b1 > 0.f) ? b1 : expm1f(b1);
            eq2[(g2 * 2 + 0) * 33 + oc2] = b0;
            eq2[(g2 * 2 + 1) * 33 + oc2] = b1;
        }
        __syncthreads();
        {
            int w8 = tid >> 5;
            int lane = tid & 31;
            #pragma unroll
            for (int q = 0; q < 2; q++) {
                int nl = w8 * 2 + q;
                float v = eq2[nl * 33 + lane] * Wn3[lane];
                v += __shfl_xor_sync(0xffffffffu, v, 16);
                v += __shfl_xor_sync(0xffffffffu, v, 8);
                v += __shfl_xor_sync(0xffffffffu, v, 4);
                v += __shfl_xor_sync(0xffffffffu, v, 2);
                v += __shfl_xor_sync(0xffffffffu, v, 1);
                if (lane == 0) out[PP + nb + nl] = v + bn3[0];
            }
        }
    }
}

// ---------------- launch ----------------
extern "C" void kernel_launch(void* const* d_in, const int* in_sizes, int n_in,
                              void* d_out, int out_size) {
    const float* x   = (const float*)d_in[0];
    const int*   ei  = (const int*)d_in[1];
    const float* ea  = (const float*)d_in[2];
    const int*   pe  = (const int*)d_in[3];
    const float* Wl1 = (const float*)d_in[4];
    const float* bl1 = (const float*)d_in[5];
    const float* Wr1 = (const float*)d_in[6];
    const float* br1 = (const float*)d_in[7];
    const float* We1 = (const float*)d_in[8];
    const float* att1= (const float*)d_in[9];
    const float* b1  = (const float*)d_in[10];
    const float* Wl2 = (const float*)d_in[11];
    const float* bl2 = (const float*)d_in[12];
    const float* Wr2 = (const float*)d_in[13];
    const float* br2 = (const float*)d_in[14];
    const float* We2 = (const float*)d_in[15];
    const float* att2= (const float*)d_in[16];
    const float* b2  = (const float*)d_in[17];
    const float* Wq1 = (const float*)d_in[18];
    const float* bq1 = (const float*)d_in[19];
    const float* Wq2 = (const float*)d_in[20];
    const float* bq2 = (const float*)d_in[21];
    const float* Wq3 = (const float*)d_in[22];
    const float* bq3 = (const float*)d_in[23];
    const float* Wn1 = (const float*)d_in[24];
    const float* bn1 = (const float*)d_in[25];
    const float* Wn2 = (const float*)d_in[26];
    const float* bn2 = (const float*)d_in[27];
    const float* Wn3 = (const float*)d_in[28];
    const float* bn3 = (const float*)d_in[29];
    float* out = (float*)d_out;

    const int* src = ei;
    const int* dst = ei + EE;

    k_init_gemm1<<<64 + NN / 16, 256>>>(x, Wl1, bl1, Wr1, br1);
    count_insert_scan_kernel<<<(EE + 255) / 256, 256>>>(dst, pe);
    scatter_scan_kernel<<<(EE + 255) / 256, 256>>>(src, dst, ea);

    gat_edge<<<592, 128>>>(We1, att1, b1, 0);
    gemm2<<<2 * G2_ROWBLOCKS, 256>>>(Wl2, bl2, Wr2, br2);
    gat_edge<<<592, 128>>>(We2, att2, b2, 1);

    heads_kernel<<<EDGE_BLOCKS + (NN + 15) / 16, 256>>>(
        pe, ea, Wq1, bq1, Wq2, bq2, Wq3, bq3,
        Wn1, bn1, Wn2, bn2, Wn3, bn3, out);
}

// round 13
// speedup vs baseline: 1.1941x; 1.1941x over previous
#include <cuda_runtime.h>
#include <math.h>

#define NN 10000
#define EE 160000
#define PP 4000
#define HT_SIZE 16384
#define HT_MASK 16383
#define NOTF 0x7fffffff

typedef unsigned long long ull;

// ---------------- f32x2 packed helpers (Blackwell) ----------------
__device__ __forceinline__ ull pack2(float lo, float hi) {
    ull r; asm("mov.b64 %0,{%1,%2};" : "=l"(r) : "f"(lo), "f"(hi)); return r;
}
__device__ __forceinline__ float2 unpack2(ull v) {
    float2 r; asm("mov.b64 {%0,%1},%2;" : "=f"(r.x), "=f"(r.y) : "l"(v)); return r;
}
__device__ __forceinline__ ull fma2(ull a, ull b, ull c) {
    ull d; asm("fma.rn.f32x2 %0,%1,%2,%3;" : "=l"(d) : "l"(a), "l"(b), "l"(c)); return d;
}
__device__ __forceinline__ ull mul2(ull a, ull b) {
    ull d; asm("mul.rn.f32x2 %0,%1,%2;" : "=l"(d) : "l"(a), "l"(b)); return d;
}
__device__ __forceinline__ ull add2(ull a, ull b) {
    ull d; asm("add.rn.f32x2 %0,%1,%2;" : "=l"(d) : "l"(a), "l"(b)); return d;
}

// ---------------- scratch (device globals; no allocation) ----------------
__device__ float g_xl[NN * 256];
__device__ float g_xr[NN * 256];
__device__ float g_h[NN * 256];
__device__ int g_cnt[NN];
__device__ int g_rowstart[NN + 1];
__device__ int g_cursor[NN];
__device__ __align__(16) float4 g_eac[EE];   // {ea0, ea1, ea2, src_bits}
__device__ int g_htk[HT_SIZE];
__device__ int g_htv[HT_SIZE];
__device__ int g_done;
__device__ int g_nctr[2];                    // work-steal counters (per gat layer)

__device__ __forceinline__ unsigned ht_hash(int key) {
    return ((unsigned)key * 2654435761u) >> 18;
}
__device__ __forceinline__ int ht_find(int key) {
    unsigned slot = ht_hash(key) & HT_MASK;
    while (true) {
        int kk = g_htk[slot];
        if (kk == key) return g_htv[slot];
        if (kk == -1) return NOTF;
        slot = (slot + 1) & HT_MASK;
    }
}

// ---------------- K1: init hash/counts (blocks 0..63) + layer-1 GEMM ----------------
__global__ __launch_bounds__(256) void k_init_gemm1(
    const float* __restrict__ X,
    const float* __restrict__ Wl, const float* __restrict__ bl,
    const float* __restrict__ Wr, const float* __restrict__ br) {
    if (blockIdx.x < 64) {
        int i = blockIdx.x * 256 + threadIdx.x;
        if (i < HT_SIZE) { g_htk[i] = -1; g_htv[i] = NOTF; }
        if (i < NN) g_cnt[i] = 0;
        if (i == 0) { g_done = 0; g_nctr[0] = 0; g_nctr[1] = 0; }
        return;
    }
    __shared__ __align__(16) float xs[8 * 16];
    int tid = threadIdx.x;
    int nb = (blockIdx.x - 64) * 16;
    if (tid < 128) {
        int i = tid / 8, k = tid % 8;
        xs[k * 16 + i] = X[(nb + i) * 8 + k];
    }
    __syncthreads();
    ull accl[8], accr[8];
    #pragma unroll
    for (int q = 0; q < 8; q++) { accl[q] = 0ULL; accr[q] = 0ULL; }
    #pragma unroll
    for (int k = 0; k < 8; k++) {
        float wl = __ldg(Wl + k * 256 + tid);
        float wr = __ldg(Wr + k * 256 + tid);
        ull wl2 = pack2(wl, wl);
        ull wr2 = pack2(wr, wr);
        const ulonglong2* xv = reinterpret_cast<const ulonglong2*>(xs + k * 16);
        #pragma unroll
        for (int q2 = 0; q2 < 4; q2++) {
            ulonglong2 a = xv[q2];
            accl[q2 * 2 + 0] = fma2(a.x, wl2, accl[q2 * 2 + 0]);
            accl[q2 * 2 + 1] = fma2(a.y, wl2, accl[q2 * 2 + 1]);
            accr[q2 * 2 + 0] = fma2(a.x, wr2, accr[q2 * 2 + 0]);
            accr[q2 * 2 + 1] = fma2(a.y, wr2, accr[q2 * 2 + 1]);
        }
    }
    float bvl = bl[tid], bvr = br[tid];
    #pragma unroll
    for (int q = 0; q < 8; q++) {
        float2 vl = unpack2(accl[q]);
        float2 vr = unpack2(accr[q]);
        g_xl[(nb + 2 * q + 0) * 256 + tid] = vl.x + bvl;
        g_xl[(nb + 2 * q + 1) * 256 + tid] = vl.y + bvl;
        g_xr[(nb + 2 * q + 0) * 256 + tid] = vr.x + bvr;
        g_xr[(nb + 2 * q + 1) * 256 + tid] = vr.y + bvr;
    }
}

// ---------------- K2: count degrees + hash-insert + (last block) prefix scan ----------------
__global__ __launch_bounds__(256) void count_insert_scan_kernel(
    const int* __restrict__ dst, const int* __restrict__ pe) {
    int e = blockIdx.x * blockDim.x + threadIdx.x;
    if (e < EE) atomicAdd(&g_cnt[dst[e]], 1);
    if (e < 2 * PP) {
        int p = e >> 1;
        int i = pe[p * 2 + 0];
        int j = pe[p * 2 + 1];
        int key = (e & 1) ? (j * NN + i) : (i * NN + j);
        unsigned slot = ht_hash(key) & HT_MASK;
        while (true) {
            int old = atomicCAS(&g_htk[slot], -1, key);
            if (old == -1 || old == key) break;
            slot = (slot + 1) & HT_MASK;
        }
    }
    __threadfence();
    __shared__ int isLast;
    if (threadIdx.x == 0) {
        int v = atomicAdd(&g_done, 1);
        isLast = (v == (int)gridDim.x - 1);
    }
    __syncthreads();
    if (!isLast) return;

    __shared__ int part[256];
    int t = threadIdx.x;
    const int CH = 40;
    int base = t * CH;
    int s = 0;
    for (int i = 0; i < CH; i++) {
        int idx = base + i;
        if (idx < NN) s += g_cnt[idx];
    }
    part[t] = s;
    __syncthreads();
    for (int off = 1; off < 256; off <<= 1) {
        int v = (t >= off) ? part[t - off] : 0;
        __syncthreads();
        part[t] += v;
        __syncthreads();
    }
    int run = (t > 0) ? part[t - 1] : 0;
    for (int i = 0; i < CH; i++) {
        int idx = base + i;
        if (idx < NN) {
            g_rowstart[idx] = run;
            g_cursor[idx] = run;
            run += g_cnt[idx];
        }
    }
    if (t == 255) g_rowstart[NN] = part[255];
}

// ---------------- K3: scatter packed edge payload into CSR + hash min-scan ----------------
__global__ void scatter_scan_kernel(const int* __restrict__ src, const int* __restrict__ dst,
                                    const float* __restrict__ ea) {
    int e = blockIdx.x * blockDim.x + threadIdx.x;
    if (e >= EE) return;
    int sN = src[e], dN = dst[e];
    float4 c;
    c.x = __ldg(ea + e * 3 + 0);
    c.y = __ldg(ea + e * 3 + 1);
    c.z = __ldg(ea + e * 3 + 2);
    c.w = __int_as_float(sN);
    int pos = atomicAdd(&g_cursor[dN], 1);
    g_eac[pos] = c;
    int key = sN * NN + dN;
    unsigned slot = ht_hash(key) & HT_MASK;
    while (true) {
        int kk = g_htk[slot];
        if (kk == -1) return;
        if (kk == key) { atomicMin(&g_htv[slot], e); return; }
        slot = (slot + 1) & HT_MASK;
    }
}

// ---------------- GATv2 edge phase: one warp per node (8 ch/lane), work-stealing,
// ---------------- 2-deep software pipeline (eac AND xl prefetched one edge ahead) ----------------
__global__ void __launch_bounds__(128, 4) gat_edge(
    const float* __restrict__ We,
    const float* __restrict__ att, const float* __restrict__ bias, int layer) {
    int l = threadIdx.x & 31;
    int ch0 = l * 8;
    int head = l >> 3;
    int hk = (l & 7) * 8;

    // packed per-lane constants (channel pairs)
    ull wv0[4], wv1[4], wv2[4], av2[4];
    #pragma unroll
    for (int k = 0; k < 4; k++) {
        wv0[k] = pack2(We[0 * 256 + ch0 + 2 * k], We[0 * 256 + ch0 + 2 * k + 1]);
        wv1[k] = pack2(We[1 * 256 + ch0 + 2 * k], We[1 * 256 + ch0 + 2 * k + 1]);
        wv2[k] = pack2(We[2 * 256 + ch0 + 2 * k], We[2 * 256 + ch0 + 2 * k + 1]);
        av2[k] = pack2(att[head * 64 + hk + 2 * k], att[head * 64 + hk + 2 * k + 1]);
    }
    const ull C06 = pack2(0.6f, 0.6f);
    const ull C04 = pack2(0.4f, 0.4f);
    const ull ABSM = 0x7FFFFFFF7FFFFFFFULL;

    while (true) {
        int node;
        if (l == 0) node = atomicAdd(&g_nctr[layer], 1);
        node = __shfl_sync(0xffffffffu, node, 0);
        if (node >= NN) break;

        ull xr2[4];
        {
            float4 ra = *reinterpret_cast<const float4*>(g_xr + node * 256 + ch0);
            float4 rb = *reinterpret_cast<const float4*>(g_xr + node * 256 + ch0 + 4);
            xr2[0] = pack2(ra.x, ra.y); xr2[1] = pack2(ra.z, ra.w);
            xr2[2] = pack2(rb.x, rb.y); xr2[3] = pack2(rb.z, rb.w);
        }
        int s0 = g_rowstart[node];
        int en = g_rowstart[node + 1];
        int last = en - 1;

        float ssum = 0.f;
        ull acc[4] = {0ULL, 0ULL, 0ULL, 0ULL};

        // 2-deep pipeline: edge sp's (eac, xl) loaded an iteration early.
        float4 c_cur, c_nxt, xa_cur, xb_cur;
        if (s0 < en) {
            c_cur = g_eac[s0];
            int sn = __float_as_int(c_cur.w);
            xa_cur = *reinterpret_cast<const float4*>(g_xl + sn * 256 + ch0);
            xb_cur = *reinterpret_cast<const float4*>(g_xl + sn * 256 + ch0 + 4);
            c_nxt = g_eac[min(s0 + 1, last)];
        }
        for (int sp = s0; sp < en; sp++) {
            // issue next edge's gathers before doing this edge's math
            int snn = __float_as_int(c_nxt.w);
            float4 xa_n = *reinterpret_cast<const float4*>(g_xl + snn * 256 + ch0);
            float4 xb_n = *reinterpret_cast<const float4*>(g_xl + snn * 256 + ch0 + 4);
            float4 c_nn = g_eac[min(sp + 2, last)];

            ull ea0 = pack2(c_cur.x, c_cur.x);
            ull ea1 = pack2(c_cur.y, c_cur.y);
            ull ea2 = pack2(c_cur.z, c_cur.z);
            ull x2[4];
            x2[0] = pack2(xa_cur.x, xa_cur.y); x2[1] = pack2(xa_cur.z, xa_cur.w);
            x2[2] = pack2(xb_cur.x, xb_cur.y); x2[3] = pack2(xb_cur.z, xb_cur.w);
            ull dot = 0ULL;
            #pragma unroll
            for (int k = 0; k < 4; k++) {
                ull b = fma2(ea2, wv2[k], fma2(ea1, wv1[k], fma2(ea0, wv0[k], xr2[k])));
                ull t = add2(x2[k], b);
                ull ab = t & ABSM;                       // |t| pairwise
                t = fma2(ab, C04, mul2(t, C06));         // leaky(t,0.2) = 0.6t+0.4|t|
                dot = fma2(t, av2[k], dot);
            }
            float2 d = unpack2(dot);
            float p = d.x + d.y;
            p += __shfl_xor_sync(0xffffffffu, p, 1);
            p += __shfl_xor_sync(0xffffffffu, p, 2);
            p += __shfl_xor_sync(0xffffffffu, p, 4);     // sum over 8 lanes of this head

            float w0 = __expf(p);                        // exact softmax w/o max-shift (logits O(1))
            ssum += w0;
            ull w2 = pack2(w0, w0);
            #pragma unroll
            for (int k = 0; k < 4; k++) acc[k] = fma2(w2, x2[k], acc[k]);

            // rotate pipeline
            c_cur = c_nxt; c_nxt = c_nn;
            xa_cur = xa_n; xb_cur = xb_n;
        }

        float inv = 1.f / (ssum + 1e-16f);
        float4 bva = *reinterpret_cast<const float4*>(bias + ch0);
        float4 bvb = *reinterpret_cast<const float4*>(bias + ch0 + 4);
        float2 a0 = unpack2(acc[0]);
        float2 a1 = unpack2(acc[1]);
        float2 a2 = unpack2(acc[2]);
        float2 a3 = unpack2(acc[3]);
        float vv[8] = {a0.x, a0.y, a1.x, a1.y, a2.x, a2.y, a3.x, a3.y};
        float bb[8] = {bva.x, bva.y, bva.z, bva.w, bvb.x, bvb.y, bvb.z, bvb.w};
        float o[8];
        #pragma unroll
        for (int k = 0; k < 8; k++) {
            float v = fmaf(vv[k], inv, bb[k]);
            o[k] = (v > 0.f) ? v : expm1f(v);
        }
        float* hp = g_h + node * 256 + ch0;
        *reinterpret_cast<float4*>(hp) = make_float4(o[0], o[1], o[2], o[3]);
        *reinterpret_cast<float4*>(hp + 4) = make_float4(o[4], o[5], o[6], o[7]);
    }
}

// ---------------- layer-2 dual GEMM: 36 rows/block -> 278 blocks = single wave at 2 blocks/SM ----------------
#define G2_ROWS 36
#define G2_STRIDE 40
#define G2_BLOCKS ((NN + G2_ROWS - 1) / G2_ROWS)   // 278
__global__ __launch_bounds__(256) void gemm2(
    const float* __restrict__ Wl, const float* __restrict__ bl,
    const float* __restrict__ Wr, const float* __restrict__ br) {
    __shared__ __align__(16) float xs[256 * G2_STRIDE];   // 40 KB
    int tid = threadIdx.x;
    int nb = blockIdx.x * G2_ROWS;
    for (int idx = tid; idx < G2_ROWS * 256; idx += 256) {
        int i = idx / 256, k = idx % 256;
        int row = nb + i;
        xs[k * G2_STRIDE + i] = (row < NN) ? g_h[row * 256 + k] : 0.f;
    }
    __syncthreads();
    ull accl[18], accr[18];
    #pragma unroll
    for (int q = 0; q < 18; q++) { accl[q] = 0ULL; accr[q] = 0ULL; }
    #pragma unroll 2
    for (int k = 0; k < 256; k++) {
        float wl = __ldg(Wl + k * 256 + tid);
        float wr = __ldg(Wr + k * 256 + tid);
        ull wl2 = pack2(wl, wl);
        ull wr2 = pack2(wr, wr);
        const ulonglong2* xv = reinterpret_cast<const ulonglong2*>(xs + k * G2_STRIDE);
        #pragma unroll
        for (int q2 = 0; q2 < 9; q2++) {
            ulonglong2 a = xv[q2];
            accl[q2 * 2 + 0] = fma2(a.x, wl2, accl[q2 * 2 + 0]);
            accl[q2 * 2 + 1] = fma2(a.y, wl2, accl[q2 * 2 + 1]);
            accr[q2 * 2 + 0] = fma2(a.x, wr2, accr[q2 * 2 + 0]);
            accr[q2 * 2 + 1] = fma2(a.y, wr2, accr[q2 * 2 + 1]);
        }
    }
    float bvl = bl[tid], bvr = br[tid];
    #pragma unroll
    for (int q = 0; q < 18; q++) {
        int r0 = nb + 2 * q, r1 = nb + 2 * q + 1;
        float2 vl = unpack2(accl[q]);
        float2 vr = unpack2(accr[q]);
        if (r0 < NN) { g_xl[r0 * 256 + tid] = vl.x + bvl; g_xr[r0 * 256 + tid] = vr.x + bvr; }
        if (r1 < NN) { g_xl[r1 * 256 + tid] = vl.y + bvl; g_xr[r1 * 256 + tid] = vr.y + bvr; }
    }
}

// ---------------- merged heads: blocks [0,250) edge head (16 edges), [250,875) node head ----------------
#define EDGE_BLOCKS (PP / 16)    // 250
__global__ __launch_bounds__(256) void heads_kernel(
    const int* __restrict__ pe, const float* __restrict__ eattr,
    const float* __restrict__ Wq1, const float* __restrict__ bq1,
    const float* __restrict__ Wq2, const float* __restrict__ bq2,
    const float* __restrict__ Wq3, const float* __restrict__ bq3,
    const float* __restrict__ Wn1, const float* __restrict__ bn1,
    const float* __restrict__ Wn2, const float* __restrict__ bn2,
    const float* __restrict__ Wn3, const float* __restrict__ bn3,
    float* __restrict__ out) {
    __shared__ __align__(16) float pool[11952];
    __shared__ int sidx[16];
    int tid = threadIdx.x;

    if (blockIdx.x < EDGE_BLOCKS) {
        float* efsT = pool;              // [k up to 520][stride 20]
        float* eq1 = pool + 10400;       // [16][64]
        float* eq2 = pool + 11424;       // [16][33]
        int pb = blockIdx.x * 16;
        if (tid < 16) {
            int p = pb + tid;
            int i = pe[p * 2 + 0];
            int j = pe[p * 2 + 1];
            sidx[tid] = min(ht_find(i * NN + j), ht_find(j * NN + i));
        }
        __syncthreads();
        #pragma unroll 1
        for (int e16 = 0; e16 < 16; e16++) {
            int p = pb + e16;
            int i = pe[p * 2 + 0];
            int j = pe[p * 2 + 1];
            int idx = sidx[e16];
            for (int t = tid; t < 515; t += 256) {
                float v;
                if (t < 256) v = g_h[i * 256 + t];
                else if (t < 512) v = g_h[j * 256 + (t - 256)];
                else v = (idx < NOTF) ? eattr[idx * 3 + (t - 512)] : 0.f;
                efsT[t * 20 + e16] = v;
            }
        }
        __syncthreads();
        {
            int oc = tid & 63;
            int grp = tid >> 6;
            ull a01 = 0ULL, a23 = 0ULL;
            const float* base = efsT + grp * 4;
            for (int k = 0; k < 515; k++) {
                float w = __ldg(Wq1 + k * 64 + oc);
                ull w2 = pack2(w, w);
                float4 ef = *reinterpret_cast<const float4*>(base + k * 20);
                a01 = fma2(pack2(ef.x, ef.y), w2, a01);
                a23 = fma2(pack2(ef.z, ef.w), w2, a23);
            }
            float bb = bq1[oc];
            float2 v01 = unpack2(a01);
            float2 v23 = unpack2(a23);
            float v[4] = {v01.x + bb, v01.y + bb, v23.x + bb, v23.y + bb};
            #pragma unroll
            for (int q = 0; q < 4; q++) {
                float a = v[q];
                a = (a > 0.f) ? a : expm1f(a);
                eq1[(grp * 4 + q) * 64 + oc] = a;
            }
        }
        __syncthreads();
        {
            int oc2 = tid & 31;
            int g2 = tid >> 5;
            ull b01 = 0ULL;
            for (int k = 0; k < 64; k++) {
                float w = Wq2[k * 32 + oc2];
                b01 = fma2(pack2(eq1[(g2 * 2 + 0) * 64 + k], eq1[(g2 * 2 + 1) * 64 + k]),
                           pack2(w, w), b01);
            }
            float bb2 = bq2[oc2];
            float2 b = unpack2(b01);
            float b0 = b.x + bb2, b1 = b.y + bb2;
            b0 = (b0 > 0.f) ? b0 : expm1f(b0);
            b1 = (b1 > 0.f) ? b1 : expm1f(b1);
            eq2[(g2 * 2 + 0) * 33 + oc2] = b0;
            eq2[(g2 * 2 + 1) * 33 + oc2] = b1;
        }
        __syncthreads();
        {
            int w8 = tid >> 5;
            int lane = tid & 31;
            #pragma unroll
            for (int q = 0; q < 2; q++) {
                int e = w8 * 2 + q;
                float v = eq2[e * 33 + lane] * Wq3[lane];
                v += __shfl_xor_sync(0xffffffffu, v, 16);
                v += __shfl_xor_sync(0xffffffffu, v, 8);
                v += __shfl_xor_sync(0xffffffffu, v, 4);
                v += __shfl_xor_sync(0xffffffffu, v, 2);
                v += __shfl_xor_sync(0xffffffffu, v, 1);
                if (lane == 0) out[pb + e] = v + bq3[0];
            }
        }
    } else {
        float* hsT = pool;               // [256][stride 20]
        float* eq1 = pool + 5120;        // [16][64]
        float* eq2 = pool + 6144;        // [16][33]
        int nb = (blockIdx.x - EDGE_BLOCKS) * 16;
        for (int t = tid; t < 16 * 256; t += 256) {
            int i = t >> 8;
            int c = t & 255;
            hsT[c * 20 + i] = g_h[(nb + i) * 256 + c];
        }
        __syncthreads();
        {
            int oc = tid & 63;
            int grp = tid >> 6;
            ull a01 = 0ULL, a23 = 0ULL;
            const float* base = hsT + grp * 4;
            for (int k = 0; k < 256; k++) {
                float w = __ldg(Wn1 + k * 64 + oc);
                ull w2 = pack2(w, w);
                float4 hv = *reinterpret_cast<const float4*>(base + k * 20);
                a01 = fma2(pack2(hv.x, hv.y), w2, a01);
                a23 = fma2(pack2(hv.z, hv.w), w2, a23);
            }
            float bb = bn1[oc];
            float2 v01 = unpack2(a01);
            float2 v23 = unpack2(a23);
            float v[4] = {v01.x + bb, v01.y + bb, v23.x + bb, v23.y + bb};
            #pragma unroll
            for (int q = 0; q < 4; q++) {
                float a = v[q];
                a = (a > 0.f) ? a : expm1f(a);
                eq1[(grp * 4 + q) * 64 + oc] = a;
            }
        }
        __syncthreads();
        {
            int oc2 = tid & 31;
            int g2 = tid >> 5;
            ull b01 = 0ULL;
            for (int k = 0; k < 64; k++) {
                float w = Wn2[k * 32 + oc2];
                b01 = fma2(pack2(eq1[(g2 * 2 + 0) * 64 + k], eq1[(g2 * 2 + 1) * 64 + k]),
                           pack2(w, w), b01);
            }
            float bb2 = bn2[oc2];
            float2 b = unpack2(b01);
            float b0 = b.x + bb2, b1 = b.y + bb2;
            b0 = (b0 > 0.f) ? b0 : expm1f(b0);
            b1 = (b1 > 0.f) ? b1 : expm1f(b1);
            eq2[(g2 * 2 + 0) * 33 + oc2] = b0;
            eq2[(g2 * 2 + 1) * 33 + oc2] = b1;
        }
        __syncthreads();
        {
            int w8 = tid >> 5;
            int lane = tid & 31;
            #pragma unroll
            for (int q = 0; q < 2; q++) {
                int nl = w8 * 2 + q;
                float v = eq2[nl * 33 + lane] * Wn3[lane];
                v += __shfl_xor_sync(0xffffffffu, v, 16);
                v += __shfl_xor_sync(0xffffffffu, v, 8);
                v += __shfl_xor_sync(0xffffffffu, v, 4);
                v += __shfl_xor_sync(0xffffffffu, v, 2);
                v += __shfl_xor_sync(0xffffffffu, v, 1);
                if (lane == 0) out[PP + nb + nl] = v + bn3[0];
            }
        }
    }
}

// ---------------- launch ----------------
extern "C" void kernel_launch(void* const* d_in, const int* in_sizes, int n_in,
                              void* d_out, int out_size) {
    const float* x   = (const float*)d_in[0];
    const int*   ei  = (const int*)d_in[1];
    const float* ea  = (const float*)d_in[2];
    const int*   pe  = (const int*)d_in[3];
    const float* Wl1 = (const float*)d_in[4];
    const float* bl1 = (const float*)d_in[5];
    const float* Wr1 = (const float*)d_in[6];
    const float* br1 = (const float*)d_in[7];
    const float* We1 = (const float*)d_in[8];
    const float* att1= (const float*)d_in[9];
    const float* b1  = (const float*)d_in[10];
    const float* Wl2 = (const float*)d_in[11];
    const float* bl2 = (const float*)d_in[12];
    const float* Wr2 = (const float*)d_in[13];
    const float* br2 = (const float*)d_in[14];
    const float* We2 = (const float*)d_in[15];
    const float* att2= (const float*)d_in[16];
    const float* b2  = (const float*)d_in[17];
    const float* Wq1 = (const float*)d_in[18];
    const float* bq1 = (const float*)d_in[19];
    const float* Wq2 = (const float*)d_in[20];
    const float* bq2 = (const float*)d_in[21];
    const float* Wq3 = (const float*)d_in[22];
    const float* bq3 = (const float*)d_in[23];
    const float* Wn1 = (const float*)d_in[24];
    const float* bn1 = (const float*)d_in[25];
    const float* Wn2 = (const float*)d_in[26];
    const float* bn2 = (const float*)d_in[27];
    const float* Wn3 = (const float*)d_in[28];
    const float* bn3 = (const float*)d_in[29];
    float* out = (float*)d_out;

    const int* src = ei;
    const int* dst = ei + EE;

    k_init_gemm1<<<64 + NN / 16, 256>>>(x, Wl1, bl1, Wr1, br1);
    count_insert_scan_kernel<<<(EE + 255) / 256, 256>>>(dst, pe);
    scatter_scan_kernel<<<(EE + 255) / 256, 256>>>(src, dst, ea);

    gat_edge<<<592, 128>>>(We1, att1, b1, 0);
    gemm2<<<G2_BLOCKS, 256>>>(Wl2, bl2, Wr2, br2);
    gat_edge<<<592, 128>>>(We2, att2, b2, 1);

    heads_kernel<<<EDGE_BLOCKS + (NN + 15) / 16, 256>>>(
        pe, ea, Wq1, bq1, Wq2, bq2, Wq3, bq3,
        Wn1, bn1, Wn2, bn2, Wn3, bn3, out);
}

// round 14
// speedup vs baseline: 1.2152x; 1.0177x over previous
#include <cuda_runtime.h>
#include <math.h>

#define NN 10000
#define EE 160000
#define PP 4000
#define HT_SIZE 16384
#define HT_MASK 16383
#define NOTF 0x7fffffff

typedef unsigned long long ull;

// ---------------- f32x2 packed helpers (Blackwell) ----------------
__device__ __forceinline__ ull pack2(float lo, float hi) {
    ull r; asm("mov.b64 %0,{%1,%2};" : "=l"(r) : "f"(lo), "f"(hi)); return r;
}
__device__ __forceinline__ float2 unpack2(ull v) {
    float2 r; asm("mov.b64 {%0,%1},%2;" : "=f"(r.x), "=f"(r.y) : "l"(v)); return r;
}
__device__ __forceinline__ ull fma2(ull a, ull b, ull c) {
    ull d; asm("fma.rn.f32x2 %0,%1,%2,%3;" : "=l"(d) : "l"(a), "l"(b), "l"(c)); return d;
}
__device__ __forceinline__ ull mul2(ull a, ull b) {
    ull d; asm("mul.rn.f32x2 %0,%1,%2;" : "=l"(d) : "l"(a), "l"(b)); return d;
}
__device__ __forceinline__ ull add2(ull a, ull b) {
    ull d; asm("add.rn.f32x2 %0,%1,%2;" : "=l"(d) : "l"(a), "l"(b)); return d;
}

// ---------------- scratch (device globals; no allocation) ----------------
__device__ float g_xl[NN * 256];
__device__ float g_xr[NN * 256];
__device__ float g_h[NN * 256];
__device__ int g_cnt[NN];
__device__ int g_rowstart[NN + 1];
__device__ int g_cursor[NN];
__device__ __align__(16) float4 g_eac[EE];   // {ea0, ea1, ea2, src_bits}
__device__ int g_htk[HT_SIZE];
__device__ int g_htv[HT_SIZE];
__device__ int g_done;
__device__ int g_nctr[2];                    // work-steal counters (per gat layer)

__device__ __forceinline__ unsigned ht_hash(int key) {
    return ((unsigned)key * 2654435761u) >> 18;
}
__device__ __forceinline__ int ht_find(int key) {
    unsigned slot = ht_hash(key) & HT_MASK;
    while (true) {
        int kk = g_htk[slot];
        if (kk == key) return g_htv[slot];
        if (kk == -1) return NOTF;
        slot = (slot + 1) & HT_MASK;
    }
}

// ---------------- K1: init hash/counts (blocks 0..63) + layer-1 GEMM ----------------
__global__ __launch_bounds__(256) void k_init_gemm1(
    const float* __restrict__ X,
    const float* __restrict__ Wl, const float* __restrict__ bl,
    const float* __restrict__ Wr, const float* __restrict__ br) {
    if (blockIdx.x < 64) {
        int i = blockIdx.x * 256 + threadIdx.x;
        if (i < HT_SIZE) { g_htk[i] = -1; g_htv[i] = NOTF; }
        if (i < NN) g_cnt[i] = 0;
        if (i == 0) { g_done = 0; g_nctr[0] = 0; g_nctr[1] = 0; }
        return;
    }
    __shared__ __align__(16) float xs[8 * 16];
    int tid = threadIdx.x;
    int nb = (blockIdx.x - 64) * 16;
    if (tid < 128) {
        int i = tid / 8, k = tid % 8;
        xs[k * 16 + i] = X[(nb + i) * 8 + k];
    }
    __syncthreads();
    ull accl[8], accr[8];
    #pragma unroll
    for (int q = 0; q < 8; q++) { accl[q] = 0ULL; accr[q] = 0ULL; }
    #pragma unroll
    for (int k = 0; k < 8; k++) {
        float wl = __ldg(Wl + k * 256 + tid);
        float wr = __ldg(Wr + k * 256 + tid);
        ull wl2 = pack2(wl, wl);
        ull wr2 = pack2(wr, wr);
        const ulonglong2* xv = reinterpret_cast<const ulonglong2*>(xs + k * 16);
        #pragma unroll
        for (int q2 = 0; q2 < 4; q2++) {
            ulonglong2 a = xv[q2];
            accl[q2 * 2 + 0] = fma2(a.x, wl2, accl[q2 * 2 + 0]);
            accl[q2 * 2 + 1] = fma2(a.y, wl2, accl[q2 * 2 + 1]);
            accr[q2 * 2 + 0] = fma2(a.x, wr2, accr[q2 * 2 + 0]);
            accr[q2 * 2 + 1] = fma2(a.y, wr2, accr[q2 * 2 + 1]);
        }
    }
    float bvl = bl[tid], bvr = br[tid];
    #pragma unroll
    for (int q = 0; q < 8; q++) {
        float2 vl = unpack2(accl[q]);
        float2 vr = unpack2(accr[q]);
        g_xl[(nb + 2 * q + 0) * 256 + tid] = vl.x + bvl;
        g_xl[(nb + 2 * q + 1) * 256 + tid] = vl.y + bvl;
        g_xr[(nb + 2 * q + 0) * 256 + tid] = vr.x + bvr;
        g_xr[(nb + 2 * q + 1) * 256 + tid] = vr.y + bvr;
    }
}

// ---------------- K2: count degrees + hash-insert + (last block) prefix scan ----------------
__global__ __launch_bounds__(256) void count_insert_scan_kernel(
    const int* __restrict__ dst, const int* __restrict__ pe) {
    int e = blockIdx.x * blockDim.x + threadIdx.x;
    if (e < EE) atomicAdd(&g_cnt[dst[e]], 1);
    if (e < 2 * PP) {
        int p = e >> 1;
        int i = pe[p * 2 + 0];
        int j = pe[p * 2 + 1];
        int key = (e & 1) ? (j * NN + i) : (i * NN + j);
        unsigned slot = ht_hash(key) & HT_MASK;
        while (true) {
            int old = atomicCAS(&g_htk[slot], -1, key);
            if (old == -1 || old == key) break;
            slot = (slot + 1) & HT_MASK;
        }
    }
    __threadfence();
    __shared__ int isLast;
    if (threadIdx.x == 0) {
        int v = atomicAdd(&g_done, 1);
        isLast = (v == (int)gridDim.x - 1);
    }
    __syncthreads();
    if (!isLast) return;

    __shared__ int part[256];
    int t = threadIdx.x;
    const int CH = 40;
    int base = t * CH;
    int s = 0;
    for (int i = 0; i < CH; i++) {
        int idx = base + i;
        if (idx < NN) s += g_cnt[idx];
    }
    part[t] = s;
    __syncthreads();
    for (int off = 1; off < 256; off <<= 1) {
        int v = (t >= off) ? part[t - off] : 0;
        __syncthreads();
        part[t] += v;
        __syncthreads();
    }
    int run = (t > 0) ? part[t - 1] : 0;
    for (int i = 0; i < CH; i++) {
        int idx = base + i;
        if (idx < NN) {
            g_rowstart[idx] = run;
            g_cursor[idx] = run;
            run += g_cnt[idx];
        }
    }
    if (t == 255) g_rowstart[NN] = part[255];
}

// ---------------- K3: scatter packed edge payload into CSR + hash min-scan ----------------
__global__ void scatter_scan_kernel(const int* __restrict__ src, const int* __restrict__ dst,
                                    const float* __restrict__ ea) {
    int e = blockIdx.x * blockDim.x + threadIdx.x;
    if (e >= EE) return;
    int sN = src[e], dN = dst[e];
    float4 c;
    c.x = __ldg(ea + e * 3 + 0);
    c.y = __ldg(ea + e * 3 + 1);
    c.z = __ldg(ea + e * 3 + 2);
    c.w = __int_as_float(sN);
    int pos = atomicAdd(&g_cursor[dN], 1);
    g_eac[pos] = c;
    int key = sN * NN + dN;
    unsigned slot = ht_hash(key) & HT_MASK;
    while (true) {
        int kk = g_htk[slot];
        if (kk == -1) return;
        if (kk == key) { atomicMin(&g_htv[slot], e); return; }
        slot = (slot + 1) & HT_MASK;
    }
}

// ---------------- GATv2 edge phase: one warp per node (8 ch/lane), work-stealing,
// ---------------- 2-deep software pipeline (eac AND xl prefetched one edge ahead) ----------------
__global__ void __launch_bounds__(128, 4) gat_edge(
    const float* __restrict__ We,
    const float* __restrict__ att, const float* __restrict__ bias, int layer) {
    int l = threadIdx.x & 31;
    int ch0 = l * 8;
    int head = l >> 3;
    int hk = (l & 7) * 8;

    // packed per-lane constants (channel pairs)
    ull wv0[4], wv1[4], wv2[4], av2[4];
    #pragma unroll
    for (int k = 0; k < 4; k++) {
        wv0[k] = pack2(We[0 * 256 + ch0 + 2 * k], We[0 * 256 + ch0 + 2 * k + 1]);
        wv1[k] = pack2(We[1 * 256 + ch0 + 2 * k], We[1 * 256 + ch0 + 2 * k + 1]);
        wv2[k] = pack2(We[2 * 256 + ch0 + 2 * k], We[2 * 256 + ch0 + 2 * k + 1]);
        av2[k] = pack2(att[head * 64 + hk + 2 * k], att[head * 64 + hk + 2 * k + 1]);
    }
    const ull C06 = pack2(0.6f, 0.6f);
    const ull C04 = pack2(0.4f, 0.4f);
    const ull ABSM = 0x7FFFFFFF7FFFFFFFULL;

    while (true) {
        int node;
        if (l == 0) node = atomicAdd(&g_nctr[layer], 1);
        node = __shfl_sync(0xffffffffu, node, 0);
        if (node >= NN) break;

        ull xr2[4];
        {
            float4 ra = *reinterpret_cast<const float4*>(g_xr + node * 256 + ch0);
            float4 rb = *reinterpret_cast<const float4*>(g_xr + node * 256 + ch0 + 4);
            xr2[0] = pack2(ra.x, ra.y); xr2[1] = pack2(ra.z, ra.w);
            xr2[2] = pack2(rb.x, rb.y); xr2[3] = pack2(rb.z, rb.w);
        }
        int s0 = g_rowstart[node];
        int en = g_rowstart[node + 1];
        int last = en - 1;

        float ssum = 0.f;
        ull acc[4] = {0ULL, 0ULL, 0ULL, 0ULL};

        // 2-deep pipeline: edge sp's (eac, xl) loaded an iteration early.
        float4 c_cur, c_nxt, xa_cur, xb_cur;
        if (s0 < en) {
            c_cur = g_eac[s0];
            int sn = __float_as_int(c_cur.w);
            xa_cur = *reinterpret_cast<const float4*>(g_xl + sn * 256 + ch0);
            xb_cur = *reinterpret_cast<const float4*>(g_xl + sn * 256 + ch0 + 4);
            c_nxt = g_eac[min(s0 + 1, last)];
        }
        for (int sp = s0; sp < en; sp++) {
            // issue next edge's gathers before doing this edge's math
            int snn = __float_as_int(c_nxt.w);
            float4 xa_n = *reinterpret_cast<const float4*>(g_xl + snn * 256 + ch0);
            float4 xb_n = *reinterpret_cast<const float4*>(g_xl + snn * 256 + ch0 + 4);
            float4 c_nn = g_eac[min(sp + 2, last)];

            ull ea0 = pack2(c_cur.x, c_cur.x);
            ull ea1 = pack2(c_cur.y, c_cur.y);
            ull ea2 = pack2(c_cur.z, c_cur.z);
            ull x2[4];
            x2[0] = pack2(xa_cur.x, xa_cur.y); x2[1] = pack2(xa_cur.z, xa_cur.w);
            x2[2] = pack2(xb_cur.x, xb_cur.y); x2[3] = pack2(xb_cur.z, xb_cur.w);
            ull dot = 0ULL;
            #pragma unroll
            for (int k = 0; k < 4; k++) {
                ull b = fma2(ea2, wv2[k], fma2(ea1, wv1[k], fma2(ea0, wv0[k], xr2[k])));
                ull t = add2(x2[k], b);
                ull ab = t & ABSM;                       // |t| pairwise
                t = fma2(ab, C04, mul2(t, C06));         // leaky(t,0.2) = 0.6t+0.4|t|
                dot = fma2(t, av2[k], dot);
            }
            float2 d = unpack2(dot);
            float p = d.x + d.y;
            p += __shfl_xor_sync(0xffffffffu, p, 1);
            p += __shfl_xor_sync(0xffffffffu, p, 2);
            p += __shfl_xor_sync(0xffffffffu, p, 4);     // sum over 8 lanes of this head

            float w0 = __expf(p);                        // exact softmax w/o max-shift (logits O(1))
            ssum += w0;
            ull w2 = pack2(w0, w0);
            #pragma unroll
            for (int k = 0; k < 4; k++) acc[k] = fma2(w2, x2[k], acc[k]);

            // rotate pipeline
            c_cur = c_nxt; c_nxt = c_nn;
            xa_cur = xa_n; xb_cur = xb_n;
        }

        float inv = 1.f / (ssum + 1e-16f);
        float4 bva = *reinterpret_cast<const float4*>(bias + ch0);
        float4 bvb = *reinterpret_cast<const float4*>(bias + ch0 + 4);
        float2 a0 = unpack2(acc[0]);
        float2 a1 = unpack2(acc[1]);
        float2 a2 = unpack2(acc[2]);
        float2 a3 = unpack2(acc[3]);
        float vv[8] = {a0.x, a0.y, a1.x, a1.y, a2.x, a2.y, a3.x, a3.y};
        float bb[8] = {bva.x, bva.y, bva.z, bva.w, bvb.x, bvb.y, bvb.z, bvb.w};
        float o[8];
        #pragma unroll
        for (int k = 0; k < 8; k++) {
            float v = fmaf(vv[k], inv, bb[k]);
            o[k] = (v > 0.f) ? v : expm1f(v);
        }
        float* hp = g_h + node * 256 + ch0;
        *reinterpret_cast<float4*>(hp) = make_float4(o[0], o[1], o[2], o[3]);
        *reinterpret_cast<float4*>(hp + 4) = make_float4(o[4], o[5], o[6], o[7]);
    }
}

// ---------------- layer-2 dual GEMM: 36 rows/block -> 278 blocks = single wave at 2 blocks/SM ----------------
#define G2_ROWS 36
#define G2_STRIDE 40
#define G2_BLOCKS ((NN + G2_ROWS - 1) / G2_ROWS)   // 278
__global__ __launch_bounds__(256) void gemm2(
    const float* __restrict__ Wl, const float* __restrict__ bl,
    const float* __restrict__ Wr, const float* __restrict__ br) {
    __shared__ __align__(16) float xs[256 * G2_STRIDE];   // 40 KB
    int tid = threadIdx.x;
    int nb = blockIdx.x * G2_ROWS;
    for (int idx = tid; idx < G2_ROWS * 256; idx += 256) {
        int i = idx / 256, k = idx % 256;
        int row = nb + i;
        xs[k * G2_STRIDE + i] = (row < NN) ? g_h[row * 256 + k] : 0.f;
    }
    __syncthreads();
    ull accl[18], accr[18];
    #pragma unroll
    for (int q = 0; q < 18; q++) { accl[q] = 0ULL; accr[q] = 0ULL; }
    #pragma unroll 2
    for (int k = 0; k < 256; k++) {
        float wl = __ldg(Wl + k * 256 + tid);
        float wr = __ldg(Wr + k * 256 + tid);
        ull wl2 = pack2(wl, wl);
        ull wr2 = pack2(wr, wr);
        const ulonglong2* xv = reinterpret_cast<const ulonglong2*>(xs + k * G2_STRIDE);
        #pragma unroll
        for (int q2 = 0; q2 < 9; q2++) {
            ulonglong2 a = xv[q2];
            accl[q2 * 2 + 0] = fma2(a.x, wl2, accl[q2 * 2 + 0]);
            accl[q2 * 2 + 1] = fma2(a.y, wl2, accl[q2 * 2 + 1]);
            accr[q2 * 2 + 0] = fma2(a.x, wr2, accr[q2 * 2 + 0]);
            accr[q2 * 2 + 1] = fma2(a.y, wr2, accr[q2 * 2 + 1]);
        }
    }
    float bvl = bl[tid], bvr = br[tid];
    #pragma unroll
    for (int q = 0; q < 18; q++) {
        int r0 = nb + 2 * q, r1 = nb + 2 * q + 1;
        float2 vl = unpack2(accl[q]);
        float2 vr = unpack2(accr[q]);
        if (r0 < NN) { g_xl[r0 * 256 + tid] = vl.x + bvl; g_xr[r0 * 256 + tid] = vr.x + bvr; }
        if (r1 < NN) { g_xl[r1 * 256 + tid] = vl.y + bvl; g_xr[r1 * 256 + tid] = vr.y + bvr; }
    }
}

// ---------------- merged heads: blocks [0,250) edge head (16 edges), [250,563) node head (32 nodes)
// ---------------- 563 blocks @ 4 blocks/SM = single wave ----------------
#define EDGE_BLOCKS (PP / 16)          // 250
#define NH_ROWS 32
#define NH_BLOCKS ((NN + NH_ROWS - 1) / NH_ROWS)   // 313
__global__ __launch_bounds__(256) void heads_kernel(
    const int* __restrict__ pe, const float* __restrict__ eattr,
    const float* __restrict__ Wq1, const float* __restrict__ bq1,
    const float* __restrict__ Wq2, const float* __restrict__ bq2,
    const float* __restrict__ Wq3, const float* __restrict__ bq3,
    const float* __restrict__ Wn1, const float* __restrict__ bn1,
    const float* __restrict__ Wn2, const float* __restrict__ bn2,
    const float* __restrict__ Wn3, const float* __restrict__ bn3,
    float* __restrict__ out) {
    __shared__ __align__(16) float pool[11952];
    __shared__ int sidx[16];
    int tid = threadIdx.x;

    if (blockIdx.x < EDGE_BLOCKS) {
        float* efsT = pool;              // [k up to 520][stride 20]
        float* eq1 = pool + 10400;       // [16][64]
        float* eq2 = pool + 11424;       // [16][33]
        int pb = blockIdx.x * 16;
        if (tid < 16) {
            int p = pb + tid;
            int i = pe[p * 2 + 0];
            int j = pe[p * 2 + 1];
            sidx[tid] = min(ht_find(i * NN + j), ht_find(j * NN + i));
        }
        __syncthreads();
        #pragma unroll 1
        for (int e16 = 0; e16 < 16; e16++) {
            int p = pb + e16;
            int i = pe[p * 2 + 0];
            int j = pe[p * 2 + 1];
            int idx = sidx[e16];
            for (int t = tid; t < 515; t += 256) {
                float v;
                if (t < 256) v = g_h[i * 256 + t];
                else if (t < 512) v = g_h[j * 256 + (t - 256)];
                else v = (idx < NOTF) ? eattr[idx * 3 + (t - 512)] : 0.f;
                efsT[t * 20 + e16] = v;
            }
        }
        __syncthreads();
        {
            int oc = tid & 63;
            int grp = tid >> 6;
            ull a01 = 0ULL, a23 = 0ULL;
            const float* base = efsT + grp * 4;
            for (int k = 0; k < 515; k++) {
                float w = __ldg(Wq1 + k * 64 + oc);
                ull w2 = pack2(w, w);
                float4 ef = *reinterpret_cast<const float4*>(base + k * 20);
                a01 = fma2(pack2(ef.x, ef.y), w2, a01);
                a23 = fma2(pack2(ef.z, ef.w), w2, a23);
            }
            float bb = bq1[oc];
            float2 v01 = unpack2(a01);
            float2 v23 = unpack2(a23);
            float v[4] = {v01.x + bb, v01.y + bb, v23.x + bb, v23.y + bb};
            #pragma unroll
            for (int q = 0; q < 4; q++) {
                float a = v[q];
                a = (a > 0.f) ? a : expm1f(a);
                eq1[(grp * 4 + q) * 64 + oc] = a;
            }
        }
        __syncthreads();
        {
            int oc2 = tid & 31;
            int g2 = tid >> 5;
            ull b01 = 0ULL;
            for (int k = 0; k < 64; k++) {
                float w = Wq2[k * 32 + oc2];
                b01 = fma2(pack2(eq1[(g2 * 2 + 0) * 64 + k], eq1[(g2 * 2 + 1) * 64 + k]),
                           pack2(w, w), b01);
            }
            float bb2 = bq2[oc2];
            float2 b = unpack2(b01);
            float b0 = b.x + bb2, b1 = b.y + bb2;
            b0 = (b0 > 0.f) ? b0 : expm1f(b0);
            b1 = (b1 > 0.f) ? b1 : expm1f(b1);
            eq2[(g2 * 2 + 0) * 33 + oc2] = b0;
            eq2[(g2 * 2 + 1) * 33 + oc2] = b1;
        }
        __syncthreads();
        {
            int w8 = tid >> 5;
            int lane = tid & 31;
            #pragma unroll
            for (int q = 0; q < 2; q++) {
                int e = w8 * 2 + q;
                float v = eq2[e * 33 + lane] * Wq3[lane];
                v += __shfl_xor_sync(0xffffffffu, v, 16);
                v += __shfl_xor_sync(0xffffffffu, v, 8);
                v += __shfl_xor_sync(0xffffffffu, v, 4);
                v += __shfl_xor_sync(0xffffffffu, v, 2);
                v += __shfl_xor_sync(0xffffffffu, v, 1);
                if (lane == 0) out[pb + e] = v + bq3[0];
            }
        }
    } else {
        // ---- node swap head: 32 nodes/block, eq2 aliases dead hsT ----
        float* hsT = pool;               // [256][36] = 9216 floats
        float* eq1 = pool + 9216;        // [32][64]  = 2048 floats (ends 11264)
        float* eq2 = pool;               // [32][33]  = 1056, aliases hsT (dead after stage 1)
        int nb = (blockIdx.x - EDGE_BLOCKS) * NH_ROWS;
        for (int t = tid; t < NH_ROWS * 256; t += 256) {
            int i = t >> 8;
            int c = t & 255;
            int row = nb + i;
            hsT[c * 36 + i] = (row < NN) ? g_h[row * 256 + c] : 0.f;
        }
        __syncthreads();
        {
            int oc = tid & 63;
            int grp = tid >> 6;          // 0..3, nodes grp*8 .. grp*8+7
            ull a[4] = {0ULL, 0ULL, 0ULL, 0ULL};
            const float* base = hsT + grp * 8;
            for (int k = 0; k < 256; k++) {
                float w = __ldg(Wn1 + k * 64 + oc);
                ull w2 = pack2(w, w);
                float4 h0 = *reinterpret_cast<const float4*>(base + k * 36);
                float4 h1 = *reinterpret_cast<const float4*>(base + k * 36 + 4);
                a[0] = fma2(pack2(h0.x, h0.y), w2, a[0]);
                a[1] = fma2(pack2(h0.z, h0.w), w2, a[1]);
                a[2] = fma2(pack2(h1.x, h1.y), w2, a[2]);
                a[3] = fma2(pack2(h1.z, h1.w), w2, a[3]);
            }
            float bb = bn1[oc];
            #pragma unroll
            for (int q = 0; q < 4; q++) {
                float2 v = unpack2(a[q]);
                float v0 = v.x + bb, v1 = v.y + bb;
                v0 = (v0 > 0.f) ? v0 : expm1f(v0);
                v1 = (v1 > 0.f) ? v1 : expm1f(v1);
                eq1[(grp * 8 + 2 * q + 0) * 64 + oc] = v0;
                eq1[(grp * 8 + 2 * q + 1) * 64 + oc] = v1;
            }
        }
        __syncthreads();
        {
            int oc2 = tid & 31;
            int g2 = tid >> 5;           // 0..7, nodes g2*4 .. g2*4+3
            ull b01 = 0ULL, b23 = 0ULL;
            for (int k = 0; k < 64; k++) {
                float w = Wn2[k * 32 + oc2];
                ull w2 = pack2(w, w);
                b01 = fma2(pack2(eq1[(g2 * 4 + 0) * 64 + k], eq1[(g2 * 4 + 1) * 64 + k]), w2, b01);
                b23 = fma2(pack2(eq1[(g2 * 4 + 2) * 64 + k], eq1[(g2 * 4 + 3) * 64 + k]), w2, b23);
            }
            float bb2 = bn2[oc2];
            float2 b0v = unpack2(b01);
            float2 b2v = unpack2(b23);
            float vq[4] = {b0v.x + bb2, b0v.y + bb2, b2v.x + bb2, b2v.y + bb2};
            #pragma unroll
            for (int q = 0; q < 4; q++) {
                float a = vq[q];
                a = (a > 0.f) ? a : expm1f(a);
                eq2[(g2 * 4 + q) * 33 + oc2] = a;
            }
        }
        __syncthreads();
        {
            int w8 = tid >> 5;
            int lane = tid & 31;
            #pragma unroll
            for (int q = 0; q < 4; q++) {
                int nl = w8 * 4 + q;
                float v = eq2[nl * 33 + lane] * Wn3[lane];
                v += __shfl_xor_sync(0xffffffffu, v, 16);
                v += __shfl_xor_sync(0xffffffffu, v, 8);
                v += __shfl_xor_sync(0xffffffffu, v, 4);
                v += __shfl_xor_sync(0xffffffffu, v, 2);
                v += __shfl_xor_sync(0xffffffffu, v, 1);
                if (lane == 0 && nb + nl < NN) out[PP + nb + nl] = v + bn3[0];
            }
        }
    }
}

// ---------------- launch ----------------
extern "C" void kernel_launch(void* const* d_in, const int* in_sizes, int n_in,
                              void* d_out, int out_size) {
    const float* x   = (const float*)d_in[0];
    const int*   ei  = (const int*)d_in[1];
    const float* ea  = (const float*)d_in[2];
    const int*   pe  = (const int*)d_in[3];
    const float* Wl1 = (const float*)d_in[4];
    const float* bl1 = (const float*)d_in[5];
    const float* Wr1 = (const float*)d_in[6];
    const float* br1 = (const float*)d_in[7];
    const float* We1 = (const float*)d_in[8];
    const float* att1= (const float*)d_in[9];
    const float* b1  = (const float*)d_in[10];
    const float* Wl2 = (const float*)d_in[11];
    const float* bl2 = (const float*)d_in[12];
    const float* Wr2 = (const float*)d_in[13];
    const float* br2 = (const float*)d_in[14];
    const float* We2 = (const float*)d_in[15];
    const float* att2= (const float*)d_in[16];
    const float* b2  = (const float*)d_in[17];
    const float* Wq1 = (const float*)d_in[18];
    const float* bq1 = (const float*)d_in[19];
    const float* Wq2 = (const float*)d_in[20];
    const float* bq2 = (const float*)d_in[21];
    const float* Wq3 = (const float*)d_in[22];
    const float* bq3 = (const float*)d_in[23];
    const float* Wn1 = (const float*)d_in[24];
    const float* bn1 = (const float*)d_in[25];
    const float* Wn2 = (const float*)d_in[26];
    const float* bn2 = (const float*)d_in[27];
    const float* Wn3 = (const float*)d_in[28];
    const float* bn3 = (const float*)d_in[29];
    float* out = (float*)d_out;

    const int* src = ei;
    const int* dst = ei + EE;

    k_init_gemm1<<<64 + NN / 16, 256>>>(x, Wl1, bl1, Wr1, br1);
    count_insert_scan_kernel<<<(EE + 255) / 256, 256>>>(dst, pe);
    scatter_scan_kernel<<<(EE + 255) / 256, 256>>>(src, dst, ea);

    gat_edge<<<592, 128>>>(We1, att1, b1, 0);
    gemm2<<<G2_BLOCKS, 256>>>(Wl2, bl2, Wr2, br2);
    gat_edge<<<592, 128>>>(We2, att2, b2, 1);

    heads_kernel<<<EDGE_BLOCKS + NH_BLOCKS, 256>>>(
        pe, ea, Wq1, bq1, Wq2, bq2, Wq3, bq3,
        Wn1, bn1, Wn2, bn2, Wn3, bn3, out);
}

// round 15
// speedup vs baseline: 1.2161x; 1.0008x over previous
#include <cuda_runtime.h>
#include <math.h>

#define NN 10000
#define EE 160000
#define PP 4000
#define HT_SIZE 16384
#define HT_MASK 16383
#define NOTF 0x7fffffff

typedef unsigned long long ull;

// ---------------- f32x2 packed helpers (Blackwell) ----------------
__device__ __forceinline__ ull pack2(float lo, float hi) {
    ull r; asm("mov.b64 %0,{%1,%2};" : "=l"(r) : "f"(lo), "f"(hi)); return r;
}
__device__ __forceinline__ float2 unpack2(ull v) {
    float2 r; asm("mov.b64 {%0,%1},%2;" : "=f"(r.x), "=f"(r.y) : "l"(v)); return r;
}
__device__ __forceinline__ ull fma2(ull a, ull b, ull c) {
    ull d; asm("fma.rn.f32x2 %0,%1,%2,%3;" : "=l"(d) : "l"(a), "l"(b), "l"(c)); return d;
}
__device__ __forceinline__ ull mul2(ull a, ull b) {
    ull d; asm("mul.rn.f32x2 %0,%1,%2;" : "=l"(d) : "l"(a), "l"(b)); return d;
}
__device__ __forceinline__ ull add2(ull a, ull b) {
    ull d; asm("add.rn.f32x2 %0,%1,%2;" : "=l"(d) : "l"(a), "l"(b)); return d;
}

// ---------------- scratch (device globals; no allocation) ----------------
__device__ float g_xl[NN * 256];
__device__ float g_xr[NN * 256];
__device__ float g_h[NN * 256];
__device__ int g_cnt[NN];
__device__ int g_rowstart[NN + 1];
__device__ int g_cursor[NN];
__device__ __align__(16) float4 g_eac[EE];   // {ea0, ea1, ea2, src_bits}
__device__ int g_htk[HT_SIZE];
__device__ int g_htv[HT_SIZE];
__device__ int g_done;
__device__ int g_ready;
__device__ int g_nctr[2];                    // work-steal counters (per gat layer)

__device__ __forceinline__ unsigned ht_hash(int key) {
    return ((unsigned)key * 2654435761u) >> 18;
}
__device__ __forceinline__ int ht_find(int key) {
    unsigned slot = ht_hash(key) & HT_MASK;
    while (true) {
        int kk = g_htk[slot];
        if (kk == key) return g_htv[slot];
        if (kk == -1) return NOTF;
        slot = (slot + 1) & HT_MASK;
    }
}

// ---------------- K1: init hash/counts/flags ----------------
__global__ __launch_bounds__(256) void init_kernel() {
    int i = blockIdx.x * 256 + threadIdx.x;
    if (i < HT_SIZE) { g_htk[i] = -1; g_htv[i] = NOTF; }
    if (i < NN) g_cnt[i] = 0;
    if (i == 0) { g_done = 0; g_ready = 0; g_nctr[0] = 0; g_nctr[1] = 0; }
}

// ---------------- K2: FUSED count+insert -> scan -> scatter -> layer-1 GEMM ----------------
// 625 blocks x 256 threads = exactly EE threads; all blocks co-resident -> spin barrier is safe.
__global__ __launch_bounds__(256) void fused_setup(
    const int* __restrict__ src, const int* __restrict__ dst,
    const int* __restrict__ pe, const float* __restrict__ ea,
    const float* __restrict__ X,
    const float* __restrict__ Wl, const float* __restrict__ bl,
    const float* __restrict__ Wr, const float* __restrict__ br) {
    int tid = threadIdx.x;
    int e = blockIdx.x * 256 + tid;          // < EE always (625*256 == EE)

    // ---- phase 1: count degree + hash-insert physical keys; keep edge payload in regs ----
    int sN = src[e], dN = dst[e];
    float ea0 = __ldg(ea + e * 3 + 0);
    float ea1 = __ldg(ea + e * 3 + 1);
    float ea2 = __ldg(ea + e * 3 + 2);
    int key = sN * NN + dN;
    atomicAdd(&g_cnt[dN], 1);
    if (e < 2 * PP) {
        int p = e >> 1;
        int i = pe[p * 2 + 0];
        int j = pe[p * 2 + 1];
        int k2 = (e & 1) ? (j * NN + i) : (i * NN + j);
        unsigned slot = ht_hash(k2) & HT_MASK;
        while (true) {
            int old = atomicCAS(&g_htk[slot], -1, k2);
            if (old == -1 || old == k2) break;
            slot = (slot + 1) & HT_MASK;
        }
    }

    // ---- grid barrier: last block scans, others spin ----
    __threadfence();
    __shared__ int isLast;
    if (tid == 0) {
        int v = atomicAdd(&g_done, 1);
        isLast = (v == (int)gridDim.x - 1);
    }
    __syncthreads();
    if (isLast) {
        __shared__ int part[256];
        const int CH = 40;
        int base = tid * CH;
        int s = 0;
        for (int i = 0; i < CH; i++) {
            int idx = base + i;
            if (idx < NN) s += g_cnt[idx];
        }
        part[tid] = s;
        __syncthreads();
        for (int off = 1; off < 256; off <<= 1) {
            int v = (tid >= off) ? part[tid - off] : 0;
            __syncthreads();
            part[tid] += v;
            __syncthreads();
        }
        int run = (tid > 0) ? part[tid - 1] : 0;
        for (int i = 0; i < CH; i++) {
            int idx = base + i;
            if (idx < NN) {
                g_rowstart[idx] = run;
                g_cursor[idx] = run;
                run += g_cnt[idx];
            }
        }
        if (tid == 255) g_rowstart[NN] = part[255];
        __syncthreads();
        __threadfence();
        if (tid == 0) atomicExch(&g_ready, 1);
    } else {
        if (tid == 0) {
            while (atomicAdd(&g_ready, 0) == 0) __nanosleep(64);
        }
        __syncthreads();
        __threadfence();
    }

    // ---- phase 2: scatter packed payload (regs, no re-read) + hash min-scan ----
    {
        float4 c = make_float4(ea0, ea1, ea2, __int_as_float(sN));
        int pos = atomicAdd(&g_cursor[dN], 1);
        g_eac[pos] = c;
        unsigned slot = ht_hash(key) & HT_MASK;
        while (true) {
            int kk = g_htk[slot];
            if (kk == -1) break;
            if (kk == key) { atomicMin(&g_htv[slot], e); break; }
            slot = (slot + 1) & HT_MASK;
        }
    }

    // ---- phase 3: layer-1 dual GEMM, block handles rows [bid*16, bid*16+16) ----
    __shared__ __align__(16) float xs[8 * 16];
    int nb = blockIdx.x * 16;
    __syncthreads();
    if (tid < 128) {
        int i = tid / 8, k = tid % 8;
        xs[k * 16 + i] = X[(nb + i) * 8 + k];
    }
    __syncthreads();
    ull accl[8], accr[8];
    #pragma unroll
    for (int q = 0; q < 8; q++) { accl[q] = 0ULL; accr[q] = 0ULL; }
    #pragma unroll
    for (int k = 0; k < 8; k++) {
        float wl = __ldg(Wl + k * 256 + tid);
        float wr = __ldg(Wr + k * 256 + tid);
        ull wl2 = pack2(wl, wl);
        ull wr2 = pack2(wr, wr);
        const ulonglong2* xv = reinterpret_cast<const ulonglong2*>(xs + k * 16);
        #pragma unroll
        for (int q2 = 0; q2 < 4; q2++) {
            ulonglong2 a = xv[q2];
            accl[q2 * 2 + 0] = fma2(a.x, wl2, accl[q2 * 2 + 0]);
            accl[q2 * 2 + 1] = fma2(a.y, wl2, accl[q2 * 2 + 1]);
            accr[q2 * 2 + 0] = fma2(a.x, wr2, accr[q2 * 2 + 0]);
            accr[q2 * 2 + 1] = fma2(a.y, wr2, accr[q2 * 2 + 1]);
        }
    }
    float bvl = bl[tid], bvr = br[tid];
    #pragma unroll
    for (int q = 0; q < 8; q++) {
        float2 vl = unpack2(accl[q]);
        float2 vr = unpack2(accr[q]);
        g_xl[(nb + 2 * q + 0) * 256 + tid] = vl.x + bvl;
        g_xl[(nb + 2 * q + 1) * 256 + tid] = vl.y + bvl;
        g_xr[(nb + 2 * q + 0) * 256 + tid] = vr.x + bvr;
        g_xr[(nb + 2 * q + 1) * 256 + tid] = vr.y + bvr;
    }
}

// ---------------- GATv2 edge phase: one warp per node (8 ch/lane), work-stealing,
// ---------------- 2-deep software pipeline (eac AND xl prefetched one edge ahead) ----------------
__global__ void __launch_bounds__(128, 4) gat_edge(
    const float* __restrict__ We,
    const float* __restrict__ att, const float* __restrict__ bias, int layer) {
    int l = threadIdx.x & 31;
    int ch0 = l * 8;
    int head = l >> 3;
    int hk = (l & 7) * 8;

    ull wv0[4], wv1[4], wv2[4], av2[4];
    #pragma unroll
    for (int k = 0; k < 4; k++) {
        wv0[k] = pack2(We[0 * 256 + ch0 + 2 * k], We[0 * 256 + ch0 + 2 * k + 1]);
        wv1[k] = pack2(We[1 * 256 + ch0 + 2 * k], We[1 * 256 + ch0 + 2 * k + 1]);
        wv2[k] = pack2(We[2 * 256 + ch0 + 2 * k], We[2 * 256 + ch0 + 2 * k + 1]);
        av2[k] = pack2(att[head * 64 + hk + 2 * k], att[head * 64 + hk + 2 * k + 1]);
    }
    const ull C06 = pack2(0.6f, 0.6f);
    const ull C04 = pack2(0.4f, 0.4f);
    const ull ABSM = 0x7FFFFFFF7FFFFFFFULL;

    while (true) {
        int node;
        if (l == 0) node = atomicAdd(&g_nctr[layer], 1);
        node = __shfl_sync(0xffffffffu, node, 0);
        if (node >= NN) break;

        ull xr2[4];
        {
            float4 ra = *reinterpret_cast<const float4*>(g_xr + node * 256 + ch0);
            float4 rb = *reinterpret_cast<const float4*>(g_xr + node * 256 + ch0 + 4);
            xr2[0] = pack2(ra.x, ra.y); xr2[1] = pack2(ra.z, ra.w);
            xr2[2] = pack2(rb.x, rb.y); xr2[3] = pack2(rb.z, rb.w);
        }
        int s0 = g_rowstart[node];
        int en = g_rowstart[node + 1];
        int last = en - 1;

        float ssum = 0.f;
        ull acc[4] = {0ULL, 0ULL, 0ULL, 0ULL};

        float4 c_cur, c_nxt, xa_cur, xb_cur;
        if (s0 < en) {
            c_cur = g_eac[s0];
            int sn = __float_as_int(c_cur.w);
            xa_cur = *reinterpret_cast<const float4*>(g_xl + sn * 256 + ch0);
            xb_cur = *reinterpret_cast<const float4*>(g_xl + sn * 256 + ch0 + 4);
            c_nxt = g_eac[min(s0 + 1, last)];
        }
        for (int sp = s0; sp < en; sp++) {
            int snn = __float_as_int(c_nxt.w);
            float4 xa_n = *reinterpret_cast<const float4*>(g_xl + snn * 256 + ch0);
            float4 xb_n = *reinterpret_cast<const float4*>(g_xl + snn * 256 + ch0 + 4);
            float4 c_nn = g_eac[min(sp + 2, last)];

            ull ea0 = pack2(c_cur.x, c_cur.x);
            ull ea1 = pack2(c_cur.y, c_cur.y);
            ull ea2 = pack2(c_cur.z, c_cur.z);
            ull x2[4];
            x2[0] = pack2(xa_cur.x, xa_cur.y); x2[1] = pack2(xa_cur.z, xa_cur.w);
            x2[2] = pack2(xb_cur.x, xb_cur.y); x2[3] = pack2(xb_cur.z, xb_cur.w);
            ull dot = 0ULL;
            #pragma unroll
            for (int k = 0; k < 4; k++) {
                ull b = fma2(ea2, wv2[k], fma2(ea1, wv1[k], fma2(ea0, wv0[k], xr2[k])));
                ull t = add2(x2[k], b);
                ull ab = t & ABSM;
                t = fma2(ab, C04, mul2(t, C06));
                dot = fma2(t, av2[k], dot);
            }
            float2 d = unpack2(dot);
            float p = d.x + d.y;
            p += __shfl_xor_sync(0xffffffffu, p, 1);
            p += __shfl_xor_sync(0xffffffffu, p, 2);
            p += __shfl_xor_sync(0xffffffffu, p, 4);

            float w0 = __expf(p);
            ssum += w0;
            ull w2 = pack2(w0, w0);
            #pragma unroll
            for (int k = 0; k < 4; k++) acc[k] = fma2(w2, x2[k], acc[k]);

            c_cur = c_nxt; c_nxt = c_nn;
            xa_cur = xa_n; xb_cur = xb_n;
        }

        float inv = 1.f / (ssum + 1e-16f);
        float4 bva = *reinterpret_cast<const float4*>(bias + ch0);
        float4 bvb = *reinterpret_cast<const float4*>(bias + ch0 + 4);
        float2 a0 = unpack2(acc[0]);
        float2 a1 = unpack2(acc[1]);
        float2 a2 = unpack2(acc[2]);
        float2 a3 = unpack2(acc[3]);
        float vv[8] = {a0.x, a0.y, a1.x, a1.y, a2.x, a2.y, a3.x, a3.y};
        float bb[8] = {bva.x, bva.y, bva.z, bva.w, bvb.x, bvb.y, bvb.z, bvb.w};
        float o[8];
        #pragma unroll
        for (int k = 0; k < 8; k++) {
            float v = fmaf(vv[k], inv, bb[k]);
            o[k] = (v > 0.f) ? v : expm1f(v);
        }
        float* hp = g_h + node * 256 + ch0;
        *reinterpret_cast<float4*>(hp) = make_float4(o[0], o[1], o[2], o[3]);
        *reinterpret_cast<float4*>(hp + 4) = make_float4(o[4], o[5], o[6], o[7]);
    }
}

// ---------------- layer-2 dual GEMM: 36 rows/block -> 278 blocks = single wave at 2 blocks/SM ----------------
#define G2_ROWS 36
#define G2_STRIDE 40
#define G2_BLOCKS ((NN + G2_ROWS - 1) / G2_ROWS)   // 278
__global__ __launch_bounds__(256) void gemm2(
    const float* __restrict__ Wl, const float* __restrict__ bl,
    const float* __restrict__ Wr, const float* __restrict__ br) {
    __shared__ __align__(16) float xs[256 * G2_STRIDE];   // 40 KB
    int tid = threadIdx.x;
    int nb = blockIdx.x * G2_ROWS;
    for (int idx = tid; idx < G2_ROWS * 256; idx += 256) {
        int i = idx / 256, k = idx % 256;
        int row = nb + i;
        xs[k * G2_STRIDE + i] = (row < NN) ? g_h[row * 256 + k] : 0.f;
    }
    __syncthreads();
    ull accl[18], accr[18];
    #pragma unroll
    for (int q = 0; q < 18; q++) { accl[q] = 0ULL; accr[q] = 0ULL; }
    #pragma unroll 2
    for (int k = 0; k < 256; k++) {
        float wl = __ldg(Wl + k * 256 + tid);
        float wr = __ldg(Wr + k * 256 + tid);
        ull wl2 = pack2(wl, wl);
        ull wr2 = pack2(wr, wr);
        const ulonglong2* xv = reinterpret_cast<const ulonglong2*>(xs + k * G2_STRIDE);
        #pragma unroll
        for (int q2 = 0; q2 < 9; q2++) {
            ulonglong2 a = xv[q2];
            accl[q2 * 2 + 0] = fma2(a.x, wl2, accl[q2 * 2 + 0]);
            accl[q2 * 2 + 1] = fma2(a.y, wl2, accl[q2 * 2 + 1]);
            accr[q2 * 2 + 0] = fma2(a.x, wr2, accr[q2 * 2 + 0]);
            accr[q2 * 2 + 1] = fma2(a.y, wr2, accr[q2 * 2 + 1]);
        }
    }
    float bvl = bl[tid], bvr = br[tid];
    #pragma unroll
    for (int q = 0; q < 18; q++) {
        int r0 = nb + 2 * q, r1 = nb + 2 * q + 1;
        float2 vl = unpack2(accl[q]);
        float2 vr = unpack2(accr[q]);
        if (r0 < NN) { g_xl[r0 * 256 + tid] = vl.x + bvl; g_xr[r0 * 256 + tid] = vr.x + bvr; }
        if (r1 < NN) { g_xl[r1 * 256 + tid] = vl.y + bvl; g_xr[r1 * 256 + tid] = vr.y + bvr; }
    }
}

// ---------------- merged heads: blocks [0,250) edge head (16 edges), [250,563) node head (32 nodes) ----------------
#define EDGE_BLOCKS (PP / 16)          // 250
#define NH_ROWS 32
#define NH_BLOCKS ((NN + NH_ROWS - 1) / NH_ROWS)   // 313
__global__ __launch_bounds__(256) void heads_kernel(
    const int* __restrict__ pe, const float* __restrict__ eattr,
    const float* __restrict__ Wq1, const float* __restrict__ bq1,
    const float* __restrict__ Wq2, const float* __restrict__ bq2,
    const float* __restrict__ Wq3, const float* __restrict__ bq3,
    const float* __restrict__ Wn1, const float* __restrict__ bn1,
    const float* __restrict__ Wn2, const float* __restrict__ bn2,
    const float* __restrict__ Wn3, const float* __restrict__ bn3,
    float* __restrict__ out) {
    __shared__ __align__(16) float pool[11952];
    __shared__ int sidx[16];
    int tid = threadIdx.x;

    if (blockIdx.x < EDGE_BLOCKS) {
        float* efsT = pool;              // [k up to 520][stride 20]
        float* eq1 = pool + 10400;       // [16][64]
        float* eq2 = pool + 11424;       // [16][33]
        int pb = blockIdx.x * 16;
        if (tid < 16) {
            int p = pb + tid;
            int i = pe[p * 2 + 0];
            int j = pe[p * 2 + 1];
            sidx[tid] = min(ht_find(i * NN + j), ht_find(j * NN + i));
        }
        __syncthreads();
        #pragma unroll 1
        for (int e16 = 0; e16 < 16; e16++) {
            int p = pb + e16;
            int i = pe[p * 2 + 0];
            int j = pe[p * 2 + 1];
            int idx = sidx[e16];
            for (int t = tid; t < 515; t += 256) {
                float v;
                if (t < 256) v = g_h[i * 256 + t];
                else if (t < 512) v = g_h[j * 256 + (t - 256)];
                else v = (idx < NOTF) ? eattr[idx * 3 + (t - 512)] : 0.f;
                efsT[t * 20 + e16] = v;
            }
        }
        __syncthreads();
        {
            int oc = tid & 63;
            int grp = tid >> 6;
            ull a01 = 0ULL, a23 = 0ULL;
            const float* base = efsT + grp * 4;
            for (int k = 0; k < 515; k++) {
                float w = __ldg(Wq1 + k * 64 + oc);
                ull w2 = pack2(w, w);
                float4 ef = *reinterpret_cast<const float4*>(base + k * 20);
                a01 = fma2(pack2(ef.x, ef.y), w2, a01);
                a23 = fma2(pack2(ef.z, ef.w), w2, a23);
            }
            float bb = bq1[oc];
            float2 v01 = unpack2(a01);
            float2 v23 = unpack2(a23);
            float v[4] = {v01.x + bb, v01.y + bb, v23.x + bb, v23.y + bb};
            #pragma unroll
            for (int q = 0; q < 4; q++) {
                float a = v[q];
                a = (a > 0.f) ? a : expm1f(a);
                eq1[(grp * 4 + q) * 64 + oc] = a;
            }
        }
        __syncthreads();
        {
            int oc2 = tid & 31;
            int g2 = tid >> 5;
            ull b01 = 0ULL;
            for (int k = 0; k < 64; k++) {
                float w = Wq2[k * 32 + oc2];
                b01 = fma2(pack2(eq1[(g2 * 2 + 0) * 64 + k], eq1[(g2 * 2 + 1) * 64 + k]),
                           pack2(w, w), b01);
            }
            float bb2 = bq2[oc2];
            float2 b = unpack2(b01);
            float b0 = b.x + bb2, b1 = b.y + bb2;
            b0 = (b0 > 0.f) ? b0 : expm1f(b0);
            b1 = (b1 > 0.f) ? b1 : expm1f(b1);
            eq2[(g2 * 2 + 0) * 33 + oc2] = b0;
            eq2[(g2 * 2 + 1) * 33 + oc2] = b1;
        }
        __syncthreads();
        {
            int w8 = tid >> 5;
            int lane = tid & 31;
            #pragma unroll
            for (int q = 0; q < 2; q++) {
                int e = w8 * 2 + q;
                float v = eq2[e * 33 + lane] * Wq3[lane];
                v += __shfl_xor_sync(0xffffffffu, v, 16);
                v += __shfl_xor_sync(0xffffffffu, v, 8);
                v += __shfl_xor_sync(0xffffffffu, v, 4);
                v += __shfl_xor_sync(0xffffffffu, v, 2);
                v += __shfl_xor_sync(0xffffffffu, v, 1);
                if (lane == 0) out[pb + e] = v + bq3[0];
            }
        }
    } else {
        float* hsT = pool;               // [256][36] = 9216 floats
        float* eq1 = pool + 9216;        // [32][64]  = 2048 floats
        float* eq2 = pool;               // [32][33], aliases dead hsT
        int nb = (blockIdx.x - EDGE_BLOCKS) * NH_ROWS;
        for (int t = tid; t < NH_ROWS * 256; t += 256) {
            int i = t >> 8;
            int c = t & 255;
            int row = nb + i;
            hsT[c * 36 + i] = (row < NN) ? g_h[row * 256 + c] : 0.f;
        }
        __syncthreads();
        {
            int oc = tid & 63;
            int grp = tid >> 6;
            ull a[4] = {0ULL, 0ULL, 0ULL, 0ULL};
            const float* base = hsT + grp * 8;
            for (int k = 0; k < 256; k++) {
                float w = __ldg(Wn1 + k * 64 + oc);
                ull w2 = pack2(w, w);
                float4 h0 = *reinterpret_cast<const float4*>(base + k * 36);
                float4 h1 = *reinterpret_cast<const float4*>(base + k * 36 + 4);
                a[0] = fma2(pack2(h0.x, h0.y), w2, a[0]);
                a[1] = fma2(pack2(h0.z, h0.w), w2, a[1]);
                a[2] = fma2(pack2(h1.x, h1.y), w2, a[2]);
                a[3] = fma2(pack2(h1.z, h1.w), w2, a[3]);
            }
            float bb = bn1[oc];
            #pragma unroll
            for (int q = 0; q < 4; q++) {
                float2 v = unpack2(a[q]);
                float v0 = v.x + bb, v1 = v.y + bb;
                v0 = (v0 > 0.f) ? v0 : expm1f(v0);
                v1 = (v1 > 0.f) ? v1 : expm1f(v1);
                eq1[(grp * 8 + 2 * q + 0) * 64 + oc] = v0;
                eq1[(grp * 8 + 2 * q + 1) * 64 + oc] = v1;
            }
        }
        __syncthreads();
        {
            int oc2 = tid & 31;
            int g2 = tid >> 5;
            ull b01 = 0ULL, b23 = 0ULL;
            for (int k = 0; k < 64; k++) {
                float w = Wn2[k * 32 + oc2];
                ull w2 = pack2(w, w);
                b01 = fma2(pack2(eq1[(g2 * 4 + 0) * 64 + k], eq1[(g2 * 4 + 1) * 64 + k]), w2, b01);
                b23 = fma2(pack2(eq1[(g2 * 4 + 2) * 64 + k], eq1[(g2 * 4 + 3) * 64 + k]), w2, b23);
            }
            float bb2 = bn2[oc2];
            float2 b0v = unpack2(b01);
            float2 b2v = unpack2(b23);
            float vq[4] = {b0v.x + bb2, b0v.y + bb2, b2v.x + bb2, b2v.y + bb2};
            #pragma unroll
            for (int q = 0; q < 4; q++) {
                float a = vq[q];
                a = (a > 0.f) ? a : expm1f(a);
                eq2[(g2 * 4 + q) * 33 + oc2] = a;
            }
        }
        __syncthreads();
        {
            int w8 = tid >> 5;
            int lane = tid & 31;
            #pragma unroll
            for (int q = 0; q < 4; q++) {
                int nl = w8 * 4 + q;
                float v = eq2[nl * 33 + lane] * Wn3[lane];
                v += __shfl_xor_sync(0xffffffffu, v, 16);
                v += __shfl_xor_sync(0xffffffffu, v, 8);
                v += __shfl_xor_sync(0xffffffffu, v, 4);
                v += __shfl_xor_sync(0xffffffffu, v, 2);
                v += __shfl_xor_sync(0xffffffffu, v, 1);
                if (lane == 0 && nb + nl < NN) out[PP + nb + nl] = v + bn3[0];
            }
        }
    }
}

// ---------------- launch ----------------
extern "C" void kernel_launch(void* const* d_in, const int* in_sizes, int n_in,
                              void* d_out, int out_size) {
    const float* x   = (const float*)d_in[0];
    const int*   ei  = (const int*)d_in[1];
    const float* ea  = (const float*)d_in[2];
    const int*   pe  = (const int*)d_in[3];
    const float* Wl1 = (const float*)d_in[4];
    const float* bl1 = (const float*)d_in[5];
    const float* Wr1 = (const float*)d_in[6];
    const float* br1 = (const float*)d_in[7];
    const float* We1 = (const float*)d_in[8];
    const float* att1= (const float*)d_in[9];
    const float* b1  = (const float*)d_in[10];
    const float* Wl2 = (const float*)d_in[11];
    const float* bl2 = (const float*)d_in[12];
    const float* Wr2 = (const float*)d_in[13];
    const float* br2 = (const float*)d_in[14];
    const float* We2 = (const float*)d_in[15];
    const float* att2= (const float*)d_in[16];
    const float* b2  = (const float*)d_in[17];
    const float* Wq1 = (const float*)d_in[18];
    const float* bq1 = (const float*)d_in[19];
    const float* Wq2 = (const float*)d_in[20];
    const float* bq2 = (const float*)d_in[21];
    const float* Wq3 = (const float*)d_in[22];
    const float* bq3 = (const float*)d_in[23];
    const float* Wn1 = (const float*)d_in[24];
    const float* bn1 = (const float*)d_in[25];
    const float* Wn2 = (const float*)d_in[26];
    const float* bn2 = (const float*)d_in[27];
    const float* Wn3 = (const float*)d_in[28];
    const float* bn3 = (const float*)d_in[29];
    float* out = (float*)d_out;

    const int* src = ei;
    const int* dst = ei + EE;

    init_kernel<<<64, 256>>>();
    fused_setup<<<EE / 256, 256>>>(src, dst, pe, ea, x, Wl1, bl1, Wr1, br1);

    gat_edge<<<592, 128>>>(We1, att1, b1, 0);
    gemm2<<<G2_BLOCKS, 256>>>(Wl2, bl2, Wr2, br2);
    gat_edge<<<592, 128>>>(We2, att2, b2, 1);

    heads_kernel<<<EDGE_BLOCKS + NH_BLOCKS, 256>>>(
        pe, ea, Wq1, bq1, Wq2, bq2, Wq3, bq3,
        Wn1, bn1, Wn2, bn2, Wn3, bn3, out);
}

// round 16
// speedup vs baseline: 1.2189x; 1.0023x over previous
#include <cuda_runtime.h>
#include <math.h>

#define NN 10000
#define EE 160000
#define PP 4000
#define HT_SIZE 16384
#define HT_MASK 16383
#define NOTF 0x7fffffff

typedef unsigned long long ull;

// ---------------- f32x2 packed helpers (Blackwell) ----------------
__device__ __forceinline__ ull pack2(float lo, float hi) {
    ull r; asm("mov.b64 %0,{%1,%2};" : "=l"(r) : "f"(lo), "f"(hi)); return r;
}
__device__ __forceinline__ float2 unpack2(ull v) {
    float2 r; asm("mov.b64 {%0,%1},%2;" : "=f"(r.x), "=f"(r.y) : "l"(v)); return r;
}
__device__ __forceinline__ ull fma2(ull a, ull b, ull c) {
    ull d; asm("fma.rn.f32x2 %0,%1,%2,%3;" : "=l"(d) : "l"(a), "l"(b), "l"(c)); return d;
}
__device__ __forceinline__ ull mul2(ull a, ull b) {
    ull d; asm("mul.rn.f32x2 %0,%1,%2;" : "=l"(d) : "l"(a), "l"(b)); return d;
}
__device__ __forceinline__ ull add2(ull a, ull b) {
    ull d; asm("add.rn.f32x2 %0,%1,%2;" : "=l"(d) : "l"(a), "l"(b)); return d;
}

// ---------------- scratch (device globals; no allocation) ----------------
__device__ float g_xl[NN * 256];
__device__ float g_xr[NN * 256];
__device__ float g_h[NN * 256];
__device__ int g_cnt[NN];
__device__ int g_rowstart[NN + 1];
__device__ int g_cursor[NN];
__device__ __align__(16) float4 g_eac[EE];   // {ea0, ea1, ea2, src_bits}
__device__ int g_htk[HT_SIZE];
__device__ int g_htv[HT_SIZE];
__device__ int g_done;
__device__ int g_ready;
__device__ int g_nctr[2];                    // work-steal counters (per gat layer)

__device__ __forceinline__ unsigned ht_hash(int key) {
    return ((unsigned)key * 2654435761u) >> 18;
}
__device__ __forceinline__ int ht_find(int key) {
    unsigned slot = ht_hash(key) & HT_MASK;
    while (true) {
        int kk = g_htk[slot];
        if (kk == key) return g_htv[slot];
        if (kk == -1) return NOTF;
        slot = (slot + 1) & HT_MASK;
    }
}

// ---------------- K1: init hash/counts/flags ----------------
__global__ __launch_bounds__(256) void init_kernel() {
    int i = blockIdx.x * 256 + threadIdx.x;
    if (i < HT_SIZE) { g_htk[i] = -1; g_htv[i] = NOTF; }
    if (i < NN) g_cnt[i] = 0;
    if (i == 0) { g_done = 0; g_ready = 0; g_nctr[0] = 0; g_nctr[1] = 0; }
}

// ---------------- K2: FUSED count+insert -> scan -> scatter -> layer-1 GEMM ----------------
// 625 blocks x 256 threads = exactly EE threads; all blocks co-resident -> spin barrier is safe.
__global__ __launch_bounds__(256) void fused_setup(
    const int* __restrict__ src, const int* __restrict__ dst,
    const int* __restrict__ pe, const float* __restrict__ ea,
    const float* __restrict__ X,
    const float* __restrict__ Wl, const float* __restrict__ bl,
    const float* __restrict__ Wr, const float* __restrict__ br) {
    int tid = threadIdx.x;
    int e = blockIdx.x * 256 + tid;          // < EE always (625*256 == EE)

    // ---- phase 1: count degree + hash-insert physical keys; keep edge payload in regs ----
    int sN = src[e], dN = dst[e];
    float ea0 = __ldg(ea + e * 3 + 0);
    float ea1 = __ldg(ea + e * 3 + 1);
    float ea2 = __ldg(ea + e * 3 + 2);
    int key = sN * NN + dN;
    atomicAdd(&g_cnt[dN], 1);
    if (e < 2 * PP) {
        int p = e >> 1;
        int i = pe[p * 2 + 0];
        int j = pe[p * 2 + 1];
        int k2 = (e & 1) ? (j * NN + i) : (i * NN + j);
        unsigned slot = ht_hash(k2) & HT_MASK;
        while (true) {
            int old = atomicCAS(&g_htk[slot], -1, k2);
            if (old == -1 || old == k2) break;
            slot = (slot + 1) & HT_MASK;
        }
    }

    // ---- grid barrier: last block scans, others spin ----
    __threadfence();
    __shared__ int isLast;
    if (tid == 0) {
        int v = atomicAdd(&g_done, 1);
        isLast = (v == (int)gridDim.x - 1);
    }
    __syncthreads();
    if (isLast) {
        __shared__ int part[256];
        const int CH = 40;
        int base = tid * CH;
        int s = 0;
        for (int i = 0; i < CH; i++) {
            int idx = base + i;
            if (idx < NN) s += g_cnt[idx];
        }
        part[tid] = s;
        __syncthreads();
        for (int off = 1; off < 256; off <<= 1) {
            int v = (tid >= off) ? part[tid - off] : 0;
            __syncthreads();
            part[tid] += v;
            __syncthreads();
        }
        int run = (tid > 0) ? part[tid - 1] : 0;
        for (int i = 0; i < CH; i++) {
            int idx = base + i;
            if (idx < NN) {
                g_rowstart[idx] = run;
                g_cursor[idx] = run;
                run += g_cnt[idx];
            }
        }
        if (tid == 255) g_rowstart[NN] = part[255];
        __syncthreads();
        __threadfence();
        if (tid == 0) atomicExch(&g_ready, 1);
    } else {
        if (tid == 0) {
            while (atomicAdd(&g_ready, 0) == 0) __nanosleep(64);
        }
        __syncthreads();
        __threadfence();
    }

    // ---- phase 2: scatter packed payload (regs, no re-read) + hash min-scan ----
    {
        float4 c = make_float4(ea0, ea1, ea2, __int_as_float(sN));
        int pos = atomicAdd(&g_cursor[dN], 1);
        g_eac[pos] = c;
        unsigned slot = ht_hash(key) & HT_MASK;
        while (true) {
            int kk = g_htk[slot];
            if (kk == -1) break;
            if (kk == key) { atomicMin(&g_htv[slot], e); break; }
            slot = (slot + 1) & HT_MASK;
        }
    }

    // ---- phase 3: layer-1 dual GEMM, block handles rows [bid*16, bid*16+16) ----
    __shared__ __align__(16) float xs[8 * 16];
    int nb = blockIdx.x * 16;
    __syncthreads();
    if (tid < 128) {
        int i = tid / 8, k = tid % 8;
        xs[k * 16 + i] = X[(nb + i) * 8 + k];
    }
    __syncthreads();
    ull accl[8], accr[8];
    #pragma unroll
    for (int q = 0; q < 8; q++) { accl[q] = 0ULL; accr[q] = 0ULL; }
    #pragma unroll
    for (int k = 0; k < 8; k++) {
        float wl = __ldg(Wl + k * 256 + tid);
        float wr = __ldg(Wr + k * 256 + tid);
        ull wl2 = pack2(wl, wl);
        ull wr2 = pack2(wr, wr);
        const ulonglong2* xv = reinterpret_cast<const ulonglong2*>(xs + k * 16);
        #pragma unroll
        for (int q2 = 0; q2 < 4; q2++) {
            ulonglong2 a = xv[q2];
            accl[q2 * 2 + 0] = fma2(a.x, wl2, accl[q2 * 2 + 0]);
            accl[q2 * 2 + 1] = fma2(a.y, wl2, accl[q2 * 2 + 1]);
            accr[q2 * 2 + 0] = fma2(a.x, wr2, accr[q2 * 2 + 0]);
            accr[q2 * 2 + 1] = fma2(a.y, wr2, accr[q2 * 2 + 1]);
        }
    }
    float bvl = bl[tid], bvr = br[tid];
    #pragma unroll
    for (int q = 0; q < 8; q++) {
        float2 vl = unpack2(accl[q]);
        float2 vr = unpack2(accr[q]);
        g_xl[(nb + 2 * q + 0) * 256 + tid] = vl.x + bvl;
        g_xl[(nb + 2 * q + 1) * 256 + tid] = vl.y + bvl;
        g_xr[(nb + 2 * q + 0) * 256 + tid] = vr.x + bvr;
        g_xr[(nb + 2 * q + 1) * 256 + tid] = vr.y + bvr;
    }
}

// ---------------- GATv2 edge phase: one warp per node (8 ch/lane), work-stealing,
// ---------------- 2-deep software pipeline (eac AND xl prefetched one edge ahead) ----------------
__global__ void __launch_bounds__(128, 4) gat_edge(
    const float* __restrict__ We,
    const float* __restrict__ att, const float* __restrict__ bias, int layer) {
    int l = threadIdx.x & 31;
    int ch0 = l * 8;
    int head = l >> 3;
    int hk = (l & 7) * 8;

    ull wv0[4], wv1[4], wv2[4], av2[4];
    #pragma unroll
    for (int k = 0; k < 4; k++) {
        wv0[k] = pack2(We[0 * 256 + ch0 + 2 * k], We[0 * 256 + ch0 + 2 * k + 1]);
        wv1[k] = pack2(We[1 * 256 + ch0 + 2 * k], We[1 * 256 + ch0 + 2 * k + 1]);
        wv2[k] = pack2(We[2 * 256 + ch0 + 2 * k], We[2 * 256 + ch0 + 2 * k + 1]);
        av2[k] = pack2(att[head * 64 + hk + 2 * k], att[head * 64 + hk + 2 * k + 1]);
    }
    const ull C06 = pack2(0.6f, 0.6f);
    const ull C04 = pack2(0.4f, 0.4f);
    const ull ABSM = 0x7FFFFFFF7FFFFFFFULL;

    while (true) {
        int node;
        if (l == 0) node = atomicAdd(&g_nctr[layer], 1);
        node = __shfl_sync(0xffffffffu, node, 0);
        if (node >= NN) break;

        ull xr2[4];
        {
            float4 ra = *reinterpret_cast<const float4*>(g_xr + node * 256 + ch0);
            float4 rb = *reinterpret_cast<const float4*>(g_xr + node * 256 + ch0 + 4);
            xr2[0] = pack2(ra.x, ra.y); xr2[1] = pack2(ra.z, ra.w);
            xr2[2] = pack2(rb.x, rb.y); xr2[3] = pack2(rb.z, rb.w);
        }
        int s0 = g_rowstart[node];
        int en = g_rowstart[node + 1];
        int last = en - 1;

        float ssum = 0.f;
        ull acc[4] = {0ULL, 0ULL, 0ULL, 0ULL};

        float4 c_cur, c_nxt, xa_cur, xb_cur;
        if (s0 < en) {
            c_cur = g_eac[s0];
            int sn = __float_as_int(c_cur.w);
            xa_cur = *reinterpret_cast<const float4*>(g_xl + sn * 256 + ch0);
            xb_cur = *reinterpret_cast<const float4*>(g_xl + sn * 256 + ch0 + 4);
            c_nxt = g_eac[min(s0 + 1, last)];
        }
        for (int sp = s0; sp < en; sp++) {
            int snn = __float_as_int(c_nxt.w);
            float4 xa_n = *reinterpret_cast<const float4*>(g_xl + snn * 256 + ch0);
            float4 xb_n = *reinterpret_cast<const float4*>(g_xl + snn * 256 + ch0 + 4);
            float4 c_nn = g_eac[min(sp + 2, last)];

            ull ea0 = pack2(c_cur.x, c_cur.x);
            ull ea1 = pack2(c_cur.y, c_cur.y);
            ull ea2 = pack2(c_cur.z, c_cur.z);
            ull x2[4];
            x2[0] = pack2(xa_cur.x, xa_cur.y); x2[1] = pack2(xa_cur.z, xa_cur.w);
            x2[2] = pack2(xb_cur.x, xb_cur.y); x2[3] = pack2(xb_cur.z, xb_cur.w);
            ull dot = 0ULL;
            #pragma unroll
            for (int k = 0; k < 4; k++) {
                ull b = fma2(ea2, wv2[k], fma2(ea1, wv1[k], fma2(ea0, wv0[k], xr2[k])));
                ull t = add2(x2[k], b);
                ull ab = t & ABSM;
                t = fma2(ab, C04, mul2(t, C06));
                dot = fma2(t, av2[k], dot);
            }
            float2 d = unpack2(dot);
            float p = d.x + d.y;
            p += __shfl_xor_sync(0xffffffffu, p, 1);
            p += __shfl_xor_sync(0xffffffffu, p, 2);
            p += __shfl_xor_sync(0xffffffffu, p, 4);

            float w0 = __expf(p);
            ssum += w0;
            ull w2 = pack2(w0, w0);
            #pragma unroll
            for (int k = 0; k < 4; k++) acc[k] = fma2(w2, x2[k], acc[k]);

            c_cur = c_nxt; c_nxt = c_nn;
            xa_cur = xa_n; xb_cur = xb_n;
        }

        float inv = 1.f / (ssum + 1e-16f);
        float4 bva = *reinterpret_cast<const float4*>(bias + ch0);
        float4 bvb = *reinterpret_cast<const float4*>(bias + ch0 + 4);
        float2 a0 = unpack2(acc[0]);
        float2 a1 = unpack2(acc[1]);
        float2 a2 = unpack2(acc[2]);
        float2 a3 = unpack2(acc[3]);
        float vv[8] = {a0.x, a0.y, a1.x, a1.y, a2.x, a2.y, a3.x, a3.y};
        float bb[8] = {bva.x, bva.y, bva.z, bva.w, bvb.x, bvb.y, bvb.z, bvb.w};
        float o[8];
        #pragma unroll
        for (int k = 0; k < 8; k++) {
            float v = fmaf(vv[k], inv, bb[k]);
            o[k] = (v > 0.f) ? v : expm1f(v);
        }
        float* hp = g_h + node * 256 + ch0;
        *reinterpret_cast<float4*>(hp) = make_float4(o[0], o[1], o[2], o[3]);
        *reinterpret_cast<float4*>(hp + 4) = make_float4(o[4], o[5], o[6], o[7]);
    }
}

// ---------------- layer-2 dual GEMM: 36 rows/block -> 278 blocks = single wave at 2 blocks/SM ----------------
#define G2_ROWS 36
#define G2_STRIDE 40
#define G2_BLOCKS ((NN + G2_ROWS - 1) / G2_ROWS)   // 278
__global__ __launch_bounds__(256) void gemm2(
    const float* __restrict__ Wl, const float* __restrict__ bl,
    const float* __restrict__ Wr, const float* __restrict__ br) {
    __shared__ __align__(16) float xs[256 * G2_STRIDE];   // 40 KB
    int tid = threadIdx.x;
    int nb = blockIdx.x * G2_ROWS;
    for (int idx = tid; idx < G2_ROWS * 256; idx += 256) {
        int i = idx / 256, k = idx % 256;
        int row = nb + i;
        xs[k * G2_STRIDE + i] = (row < NN) ? g_h[row * 256 + k] : 0.f;
    }
    __syncthreads();
    ull accl[18], accr[18];
    #pragma unroll
    for (int q = 0; q < 18; q++) { accl[q] = 0ULL; accr[q] = 0ULL; }
    #pragma unroll 2
    for (int k = 0; k < 256; k++) {
        float wl = __ldg(Wl + k * 256 + tid);
        float wr = __ldg(Wr + k * 256 + tid);
        ull wl2 = pack2(wl, wl);
        ull wr2 = pack2(wr, wr);
        const ulonglong2* xv = reinterpret_cast<const ulonglong2*>(xs + k * G2_STRIDE);
        #pragma unroll
        for (int q2 = 0; q2 < 9; q2++) {
            ulonglong2 a = xv[q2];
            accl[q2 * 2 + 0] = fma2(a.x, wl2, accl[q2 * 2 + 0]);
            accl[q2 * 2 + 1] = fma2(a.y, wl2, accl[q2 * 2 + 1]);
            accr[q2 * 2 + 0] = fma2(a.x, wr2, accr[q2 * 2 + 0]);
            accr[q2 * 2 + 1] = fma2(a.y, wr2, accr[q2 * 2 + 1]);
        }
    }
    float bvl = bl[tid], bvr = br[tid];
    #pragma unroll
    for (int q = 0; q < 18; q++) {
        int r0 = nb + 2 * q, r1 = nb + 2 * q + 1;
        float2 vl = unpack2(accl[q]);
        float2 vr = unpack2(accr[q]);
        if (r0 < NN) { g_xl[r0 * 256 + tid] = vl.x + bvl; g_xr[r0 * 256 + tid] = vr.x + bvr; }
        if (r1 < NN) { g_xl[r1 * 256 + tid] = vl.y + bvl; g_xr[r1 * 256 + tid] = vr.y + bvr; }
    }
}

// ---------------- merged heads: blocks [0,250) edge head (16 edges), [250,563) node head (32 nodes) ----------------
#define EDGE_BLOCKS (PP / 16)          // 250
#define NH_ROWS 32
#define NH_BLOCKS ((NN + NH_ROWS - 1) / NH_ROWS)   // 313
__global__ __launch_bounds__(256) void heads_kernel(
    const int* __restrict__ pe, const float* __restrict__ eattr,
    const float* __restrict__ Wq1, const float* __restrict__ bq1,
    const float* __restrict__ Wq2, const float* __restrict__ bq2,
    const float* __restrict__ Wq3, const float* __restrict__ bq3,
    const float* __restrict__ Wn1, const float* __restrict__ bn1,
    const float* __restrict__ Wn2, const float* __restrict__ bn2,
    const float* __restrict__ Wn3, const float* __restrict__ bn3,
    float* __restrict__ out) {
    __shared__ __align__(16) float pool[11952];
    __shared__ int sidx[16];
    int tid = threadIdx.x;

    if (blockIdx.x < EDGE_BLOCKS) {
        float* efsT = pool;              // [k up to 520][stride 20]
        float* eq1 = pool + 10400;       // [16][64]
        float* eq2 = pool + 11424;       // [16][33]
        int pb = blockIdx.x * 16;
        if (tid < 16) {
            int p = pb + tid;
            int i = pe[p * 2 + 0];
            int j = pe[p * 2 + 1];
            sidx[tid] = min(ht_find(i * NN + j), ht_find(j * NN + i));
        }
        __syncthreads();
        #pragma unroll 1
        for (int e16 = 0; e16 < 16; e16++) {
            int p = pb + e16;
            int i = pe[p * 2 + 0];
            int j = pe[p * 2 + 1];
            int idx = sidx[e16];
            for (int t = tid; t < 515; t += 256) {
                float v;
                if (t < 256) v = g_h[i * 256 + t];
                else if (t < 512) v = g_h[j * 256 + (t - 256)];
                else v = (idx < NOTF) ? eattr[idx * 3 + (t - 512)] : 0.f;
                efsT[t * 20 + e16] = v;
            }
        }
        __syncthreads();
        {
            int oc = tid & 63;
            int grp = tid >> 6;
            ull a01 = 0ULL, a23 = 0ULL;
            const float* base = efsT + grp * 4;
            for (int k = 0; k < 515; k++) {
                float w = __ldg(Wq1 + k * 64 + oc);
                ull w2 = pack2(w, w);
                float4 ef = *reinterpret_cast<const float4*>(base + k * 20);
                a01 = fma2(pack2(ef.x, ef.y), w2, a01);
                a23 = fma2(pack2(ef.z, ef.w), w2, a23);
            }
            float bb = bq1[oc];
            float2 v01 = unpack2(a01);
            float2 v23 = unpack2(a23);
            float v[4] = {v01.x + bb, v01.y + bb, v23.x + bb, v23.y + bb};
            #pragma unroll
            for (int q = 0; q < 4; q++) {
                float a = v[q];
                a = (a > 0.f) ? a : expm1f(a);
                eq1[(grp * 4 + q) * 64 + oc] = a;
            }
        }
        __syncthreads();
        {
            int oc2 = tid & 31;
            int g2 = tid >> 5;
            ull b01 = 0ULL;
            for (int k = 0; k < 64; k++) {
                float w = Wq2[k * 32 + oc2];
                b01 = fma2(pack2(eq1[(g2 * 2 + 0) * 64 + k], eq1[(g2 * 2 + 1) * 64 + k]),
                           pack2(w, w), b01);
            }
            float bb2 = bq2[oc2];
            float2 b = unpack2(b01);
            float b0 = b.x + bb2, b1 = b.y + bb2;
            b0 = (b0 > 0.f) ? b0 : expm1f(b0);
            b1 = (b1 > 0.f) ? b1 : expm1f(b1);
            eq2[(g2 * 2 + 0) * 33 + oc2] = b0;
            eq2[(g2 * 2 + 1) * 33 + oc2] = b1;
        }
        __syncthreads();
        {
            int w8 = tid >> 5;
            int lane = tid & 31;
            #pragma unroll
            for (int q = 0; q < 2; q++) {
                int e = w8 * 2 + q;
                float v = eq2[e * 33 + lane] * Wq3[lane];
                v += __shfl_xor_sync(0xffffffffu, v, 16);
                v += __shfl_xor_sync(0xffffffffu, v, 8);
                v += __shfl_xor_sync(0xffffffffu, v, 4);
                v += __shfl_xor_sync(0xffffffffu, v, 2);
                v += __shfl_xor_sync(0xffffffffu, v, 1);
                if (lane == 0) out[pb + e] = v + bq3[0];
            }
        }
    } else {
        float* hsT = pool;               // [256][36] = 9216 floats
        float* eq1 = pool + 9216;        // [32][64]  = 2048 floats
        float* eq2 = pool;               // [32][33], aliases dead hsT
        int nb = (blockIdx.x - EDGE_BLOCKS) * NH_ROWS;
        for (int t = tid; t < NH_ROWS * 256; t += 256) {
            int i = t >> 8;
            int c = t & 255;
            int row = nb + i;
            hsT[c * 36 + i] = (row < NN) ? g_h[row * 256 + c] : 0.f;
        }
        __syncthreads();
        {
            int oc = tid & 63;
            int grp = tid >> 6;
            ull a[4] = {0ULL, 0ULL, 0ULL, 0ULL};
            const float* base = hsT + grp * 8;
            for (int k = 0; k < 256; k++) {
                float w = __ldg(Wn1 + k * 64 + oc);
                ull w2 = pack2(w, w);
                float4 h0 = *reinterpret_cast<const float4*>(base + k * 36);
                float4 h1 = *reinterpret_cast<const float4*>(base + k * 36 + 4);
                a[0] = fma2(pack2(h0.x, h0.y), w2, a[0]);
                a[1] = fma2(pack2(h0.z, h0.w), w2, a[1]);
                a[2] = fma2(pack2(h1.x, h1.y), w2, a[2]);
                a[3] = fma2(pack2(h1.z, h1.w), w2, a[3]);
            }
            float bb = bn1[oc];
            #pragma unroll
            for (int q = 0; q < 4; q++) {
                float2 v = unpack2(a[q]);
                float v0 = v.x + bb, v1 = v.y + bb;
                v0 = (v0 > 0.f) ? v0 : expm1f(v0);
                v1 = (v1 > 0.f) ? v1 : expm1f(v1);
                eq1[(grp * 8 + 2 * q + 0) * 64 + oc] = v0;
                eq1[(grp * 8 + 2 * q + 1) * 64 + oc] = v1;
            }
        }
        __syncthreads();
        {
            int oc2 = tid & 31;
            int g2 = tid >> 5;
            ull b01 = 0ULL, b23 = 0ULL;
            for (int k = 0; k < 64; k++) {
                float w = Wn2[k * 32 + oc2];
                ull w2 = pack2(w, w);
                b01 = fma2(pack2(eq1[(g2 * 4 + 0) * 64 + k], eq1[(g2 * 4 + 1) * 64 + k]), w2, b01);
                b23 = fma2(pack2(eq1[(g2 * 4 + 2) * 64 + k], eq1[(g2 * 4 + 3) * 64 + k]), w2, b23);
            }
            float bb2 = bn2[oc2];
            float2 b0v = unpack2(b01);
            float2 b2v = unpack2(b23);
            float vq[4] = {b0v.x + bb2, b0v.y + bb2, b2v.x + bb2, b2v.y + bb2};
            #pragma unroll
            for (int q = 0; q < 4; q++) {
                float a = vq[q];
                a = (a > 0.f) ? a : expm1f(a);
                eq2[(g2 * 4 + q) * 33 + oc2] = a;
            }
        }
        __syncthreads();
        {
            int w8 = tid >> 5;
            int lane = tid & 31;
            #pragma unroll
            for (int q = 0; q < 4; q++) {
                int nl = w8 * 4 + q;
                float v = eq2[nl * 33 + lane] * Wn3[lane];
                v += __shfl_xor_sync(0xffffffffu, v, 16);
                v += __shfl_xor_sync(0xffffffffu, v, 8);
                v += __shfl_xor_sync(0xffffffffu, v, 4);
                v += __shfl_xor_sync(0xffffffffu, v, 2);
                v += __shfl_xor_sync(0xffffffffu, v, 1);
                if (lane == 0 && nb + nl < NN) out[PP + nb + nl] = v + bn3[0];
            }
        }
    }
}

// ---------------- launch ----------------
extern "C" void kernel_launch(void* const* d_in, const int* in_sizes, int n_in,
                              void* d_out, int out_size) {
    const float* x   = (const float*)d_in[0];
    const int*   ei  = (const int*)d_in[1];
    const float* ea  = (const float*)d_in[2];
    const int*   pe  = (const int*)d_in[3];
    const float* Wl1 = (const float*)d_in[4];
    const float* bl1 = (const float*)d_in[5];
    const float* Wr1 = (const float*)d_in[6];
    const float* br1 = (const float*)d_in[7];
    const float* We1 = (const float*)d_in[8];
    const float* att1= (const float*)d_in[9];
    const float* b1  = (const float*)d_in[10];
    const float* Wl2 = (const float*)d_in[11];
    const float* bl2 = (const float*)d_in[12];
    const float* Wr2 = (const float*)d_in[13];
    const float* br2 = (const float*)d_in[14];
    const float* We2 = (const float*)d_in[15];
    const float* att2= (const float*)d_in[16];
    const float* b2  = (const float*)d_in[17];
    const float* Wq1 = (const float*)d_in[18];
    const float* bq1 = (const float*)d_in[19];
    const float* Wq2 = (const float*)d_in[20];
    const float* bq2 = (const float*)d_in[21];
    const float* Wq3 = (const float*)d_in[22];
    const float* bq3 = (const float*)d_in[23];
    const float* Wn1 = (const float*)d_in[24];
    const float* bn1 = (const float*)d_in[25];
    const float* Wn2 = (const float*)d_in[26];
    const float* bn2 = (const float*)d_in[27];
    const float* Wn3 = (const float*)d_in[28];
    const float* bn3 = (const float*)d_in[29];
    float* out = (float*)d_out;

    const int* src = ei;
    const int* dst = ei + EE;

    init_kernel<<<64, 256>>>();
    fused_setup<<<EE / 256, 256>>>(src, dst, pe, ea, x, Wl1, bl1, Wr1, br1);

    gat_edge<<<592, 128>>>(We1, att1, b1, 0);
    gemm2<<<G2_BLOCKS, 256>>>(Wl2, bl2, Wr2, br2);
    gat_edge<<<592, 128>>>(We2, att2, b2, 1);

    heads_kernel<<<EDGE_BLOCKS + NH_BLOCKS, 256>>>(
        pe, ea, Wq1, bq1, Wq2, bq2, Wq3, bq3,
        Wn1, bn1, Wn2, bn2, Wn3, bn3, out);
}